// round 4
// baseline (speedup 1.0000x reference)
#include <cuda_runtime.h>

#define BATCH  2
#define CH     512
#define NTOKB  4096              // tokens per batch (H*W)
#define NTOK   (BATCH * NTOKB)   // 8192
#define NGROUP 32
#define CPG    (CH / NGROUP)     // 16
#define EPS    1e-5f
#define SCALE  0.04419417382415922f   // 1/sqrt(512)

// ---------------- scratch (device globals; no allocations allowed) ----------
__device__ float g_t[(size_t)NTOK * CH];                 // normalized tokens [B*N, C]
__device__ float g_q[(size_t)NTOK * CH];
__device__ float g_k[(size_t)NTOK * CH];
__device__ float g_v[(size_t)NTOK * CH];
__device__ float g_o[(size_t)NTOK * CH];
__device__ float g_s[(size_t)BATCH * NTOKB * NTOKB];     // attention scores, 128 MB

// ---------------- GroupNorm + transpose to [B, N, C] ------------------------
__global__ __launch_bounds__(512) void gn_kernel(
    const float* __restrict__ x, const float* __restrict__ gw,
    const float* __restrict__ gb)
{
    const int b = blockIdx.x >> 5;
    const int g = blockIdx.x & 31;
    const float* xp = x + ((size_t)b * CH + (size_t)g * CPG) * NTOKB;
    const int NEL = CPG * NTOKB;   // 65536

    float s = 0.f, ss = 0.f;
    for (int i = threadIdx.x; i < NEL; i += 512) {
        float v = xp[i]; s += v; ss += v * v;
    }
    __shared__ float rs[16], rss[16], bc[2];
#pragma unroll
    for (int o = 16; o > 0; o >>= 1) {
        s  += __shfl_xor_sync(0xffffffffu, s, o);
        ss += __shfl_xor_sync(0xffffffffu, ss, o);
    }
    if ((threadIdx.x & 31) == 0) { rs[threadIdx.x >> 5] = s; rss[threadIdx.x >> 5] = ss; }
    __syncthreads();
    if (threadIdx.x < 32) {
        s  = (threadIdx.x < 16) ? rs[threadIdx.x]  : 0.f;
        ss = (threadIdx.x < 16) ? rss[threadIdx.x] : 0.f;
#pragma unroll
        for (int o = 8; o > 0; o >>= 1) {
            s  += __shfl_xor_sync(0xffffffffu, s, o);
            ss += __shfl_xor_sync(0xffffffffu, ss, o);
        }
        if (threadIdx.x == 0) {
            float mean = s / (float)NEL;
            float var  = ss / (float)NEL - mean * mean;
            bc[0] = mean;
            bc[1] = rsqrtf(var + EPS);
        }
    }
    __syncthreads();
    const float mean = bc[0], inv = bc[1];
    for (int i = threadIdx.x; i < NEL; i += 512) {
        int cl = i >> 12;           // /4096
        int n  = i & (NTOKB - 1);
        int c  = g * CPG + cl;
        float v = (xp[i] - mean) * inv * gw[c] + gb[c];
        g_t[((size_t)b * NTOKB + n) * CH + c] = v;
    }
}

// ---------------- NT SGEMM:  C[m,n] = alpha * sum_k A[m,k] * B[n,k] + bias[n]
// A row-major [M,K] (lda=K), B row-major [Nout,K] (ldb=K). Tiles 64x64x16.
__global__ __launch_bounds__(256) void gemm_nt(
    const float* __restrict__ A, const float* __restrict__ B,
    const float* __restrict__ bias, float* __restrict__ Cc,
    int K, int ldc, float alpha,
    size_t aStride, size_t bStride, size_t cStride)
{
    A  += (size_t)blockIdx.z * aStride;
    B  += (size_t)blockIdx.z * bStride;
    Cc += (size_t)blockIdx.z * cStride;
    const int m0 = blockIdx.y * 64;
    const int n0 = blockIdx.x * 64;

    __shared__ float As[16][68];
    __shared__ float Bs[16][68];

    const int tid = threadIdx.x;
    const int tx = tid & 15, ty = tid >> 4;
    const int lc = tid & 15, lr = tid >> 4;

    const float* Ap = A + (size_t)(m0 + lr) * K + lc;
    const float* Bp = B + (size_t)(n0 + lr) * K + lc;

    float ar[4], br[4];
#pragma unroll
    for (int u = 0; u < 4; u++) {
        ar[u] = Ap[(size_t)(16 * u) * K];
        br[u] = Bp[(size_t)(16 * u) * K];
    }

    float acc[4][4] = {};
    for (int kt = 0; kt < K; kt += 16) {
#pragma unroll
        for (int u = 0; u < 4; u++) {
            As[lc][lr + 16 * u] = ar[u];
            Bs[lc][lr + 16 * u] = br[u];
        }
        __syncthreads();
        if (kt + 16 < K) {
            Ap += 16; Bp += 16;
#pragma unroll
            for (int u = 0; u < 4; u++) {
                ar[u] = Ap[(size_t)(16 * u) * K];
                br[u] = Bp[(size_t)(16 * u) * K];
            }
        }
#pragma unroll
        for (int kk = 0; kk < 16; kk++) {
            float4 a4 = *(const float4*)&As[kk][ty * 4];
            float4 b4 = *(const float4*)&Bs[kk][tx * 4];
            float av[4] = {a4.x, a4.y, a4.z, a4.w};
            float bv[4] = {b4.x, b4.y, b4.z, b4.w};
#pragma unroll
            for (int i = 0; i < 4; i++)
#pragma unroll
                for (int j = 0; j < 4; j++)
                    acc[i][j] += av[i] * bv[j];
        }
        __syncthreads();
    }

    float bb[4];
#pragma unroll
    for (int j = 0; j < 4; j++)
        bb[j] = bias ? bias[n0 + tx * 4 + j] : 0.f;
#pragma unroll
    for (int i = 0; i < 4; i++) {
        float4 r;
        r.x = alpha * acc[i][0] + bb[0];
        r.y = alpha * acc[i][1] + bb[1];
        r.z = alpha * acc[i][2] + bb[2];
        r.w = alpha * acc[i][3] + bb[3];
        *(float4*)&Cc[(size_t)(m0 + ty * 4 + i) * ldc + n0 + tx * 4] = r;
    }
}

// ---------------- NN SGEMM:  C[m,n] = sum_k A[m,k] * B[k,n]  (A lda=K) ------
__global__ __launch_bounds__(256) void gemm_nn(
    const float* __restrict__ A, const float* __restrict__ B,
    float* __restrict__ Cc, int K, int ldb, int ldc,
    size_t aStride, size_t bStride, size_t cStride)
{
    A  += (size_t)blockIdx.z * aStride;
    B  += (size_t)blockIdx.z * bStride;
    Cc += (size_t)blockIdx.z * cStride;
    const int m0 = blockIdx.y * 64;
    const int n0 = blockIdx.x * 64;

    __shared__ float As[16][68];
    __shared__ float Bs[16][68];

    const int tid = threadIdx.x;
    const int tx = tid & 15, ty = tid >> 4;
    const int lc = tid & 15, lr = tid >> 4;          // A loader
    const int bcol = tid & 63, brow = tid >> 6;      // B loader

    const float* Ap = A + (size_t)(m0 + lr) * K + lc;
    const float* Bp = B + (size_t)brow * ldb + n0 + bcol;

    float ar[4], br[4];
#pragma unroll
    for (int u = 0; u < 4; u++) {
        ar[u] = Ap[(size_t)(16 * u) * K];
        br[u] = Bp[(size_t)(4 * u) * ldb];
    }

    float acc[4][4] = {};
    for (int kt = 0; kt < K; kt += 16) {
#pragma unroll
        for (int u = 0; u < 4; u++) {
            As[lc][lr + 16 * u] = ar[u];
            Bs[brow + 4 * u][bcol] = br[u];
        }
        __syncthreads();
        if (kt + 16 < K) {
            Ap += 16; Bp += (size_t)16 * ldb;
#pragma unroll
            for (int u = 0; u < 4; u++) {
                ar[u] = Ap[(size_t)(16 * u) * K];
                br[u] = Bp[(size_t)(4 * u) * ldb];
            }
        }
#pragma unroll
        for (int kk = 0; kk < 16; kk++) {
            float4 a4 = *(const float4*)&As[kk][ty * 4];
            float4 b4 = *(const float4*)&Bs[kk][tx * 4];
            float av[4] = {a4.x, a4.y, a4.z, a4.w};
            float bv[4] = {b4.x, b4.y, b4.z, b4.w};
#pragma unroll
            for (int i = 0; i < 4; i++)
#pragma unroll
                for (int j = 0; j < 4; j++)
                    acc[i][j] += av[i] * bv[j];
        }
        __syncthreads();
    }
#pragma unroll
    for (int i = 0; i < 4; i++) {
        float4 r;
        r.x = acc[i][0]; r.y = acc[i][1]; r.z = acc[i][2]; r.w = acc[i][3];
        *(float4*)&Cc[(size_t)(m0 + ty * 4 + i) * ldc + n0 + tx * 4] = r;
    }
}

// ---------------- out-proj NT gemm + bias + residual + transpose to BCHW ----
__global__ __launch_bounds__(256) void gemm_out(
    const float* __restrict__ A /* g_o [B*N, C] */, const float* __restrict__ Wo,
    const float* __restrict__ bo, const float* __restrict__ x,
    float* __restrict__ out)
{
    const int K = CH;
    const int m0 = blockIdx.y * 64;
    const int n0 = blockIdx.x * 64;

    __shared__ float As[16][68];
    __shared__ float Bs[16][68];

    const int tid = threadIdx.x;
    const int tx = tid & 15, ty = tid >> 4;
    const int lc = tid & 15, lr = tid >> 4;

    const float* Ap = A  + (size_t)(m0 + lr) * K + lc;
    const float* Bp = Wo + (size_t)(n0 + lr) * K + lc;

    float ar[4], br[4];
#pragma unroll
    for (int u = 0; u < 4; u++) {
        ar[u] = Ap[(size_t)(16 * u) * K];
        br[u] = Bp[(size_t)(16 * u) * K];
    }

    float acc[4][4] = {};
    for (int kt = 0; kt < K; kt += 16) {
#pragma unroll
        for (int u = 0; u < 4; u++) {
            As[lc][lr + 16 * u] = ar[u];
            Bs[lc][lr + 16 * u] = br[u];
        }
        __syncthreads();
        if (kt + 16 < K) {
            Ap += 16; Bp += 16;
#pragma unroll
            for (int u = 0; u < 4; u++) {
                ar[u] = Ap[(size_t)(16 * u) * K];
                br[u] = Bp[(size_t)(16 * u) * K];
            }
        }
#pragma unroll
        for (int kk = 0; kk < 16; kk++) {
            float4 a4 = *(const float4*)&As[kk][ty * 4];
            float4 b4 = *(const float4*)&Bs[kk][tx * 4];
            float av[4] = {a4.x, a4.y, a4.z, a4.w};
            float bv[4] = {b4.x, b4.y, b4.z, b4.w};
#pragma unroll
            for (int i = 0; i < 4; i++)
#pragma unroll
                for (int j = 0; j < 4; j++)
                    acc[i][j] += av[i] * bv[j];
        }
        __syncthreads();
    }
#pragma unroll
    for (int j = 0; j < 4; j++) {
        const int col = n0 + tx * 4 + j;     // channel
        const float bb = bo[col];
#pragma unroll
        for (int i = 0; i < 4; i++) {
            const int row = m0 + ty * 4 + i; // global token
            const int b = row >> 12;
            const int n = row & (NTOKB - 1);
            const size_t idx = ((size_t)(b * CH + col)) * NTOKB + n;
            out[idx] = acc[i][j] + bb + x[idx];
        }
    }
}

// ---------------- row softmax over the last axis (4096) ---------------------
__global__ __launch_bounds__(256) void softmax_kernel(float* __restrict__ s)
{
    float* p = s + (size_t)blockIdx.x * NTOKB;
    const int tid = threadIdx.x;
    float v[16];
    float m = -1e30f;
#pragma unroll
    for (int i = 0; i < 16; i++) { v[i] = p[i * 256 + tid]; m = fmaxf(m, v[i]); }

    __shared__ float sh[8], bcv[1];
#pragma unroll
    for (int o = 16; o > 0; o >>= 1) m = fmaxf(m, __shfl_xor_sync(0xffffffffu, m, o));
    if ((tid & 31) == 0) sh[tid >> 5] = m;
    __syncthreads();
    if (tid < 32) {
        float t = (tid < 8) ? sh[tid] : -1e30f;
#pragma unroll
        for (int o = 4; o > 0; o >>= 1) t = fmaxf(t, __shfl_xor_sync(0xffffffffu, t, o));
        if (tid == 0) bcv[0] = t;
    }
    __syncthreads();
    const float M = bcv[0];

    float sum = 0.f;
#pragma unroll
    for (int i = 0; i < 16; i++) { v[i] = __expf(v[i] - M); sum += v[i]; }
    __syncthreads();   // everyone has read bcv/sh before reuse
#pragma unroll
    for (int o = 16; o > 0; o >>= 1) sum += __shfl_xor_sync(0xffffffffu, sum, o);
    if ((tid & 31) == 0) sh[tid >> 5] = sum;
    __syncthreads();
    if (tid < 32) {
        float t = (tid < 8) ? sh[tid] : 0.f;
#pragma unroll
        for (int o = 4; o > 0; o >>= 1) t += __shfl_xor_sync(0xffffffffu, t, o);
        if (tid == 0) bcv[0] = 1.f / t;
    }
    __syncthreads();
    const float inv = bcv[0];
#pragma unroll
    for (int i = 0; i < 16; i++) p[i * 256 + tid] = v[i] * inv;
}

// ---------------- launch ----------------------------------------------------
extern "C" void kernel_launch(void* const* d_in, const int* in_sizes, int n_in,
                              void* d_out, int out_size)
{
    const float* x  = (const float*)d_in[0];
    const float* gw = (const float*)d_in[1];
    const float* gb = (const float*)d_in[2];
    const float* wq = (const float*)d_in[3];
    const float* bq = (const float*)d_in[4];
    const float* wk = (const float*)d_in[5];
    const float* bk = (const float*)d_in[6];
    const float* wv = (const float*)d_in[7];
    const float* bv = (const float*)d_in[8];
    const float* wo = (const float*)d_in[9];
    const float* bo = (const float*)d_in[10];
    float* out = (float*)d_out;

    float *t, *q, *k, *v, *o, *s;
    cudaGetSymbolAddress((void**)&t, g_t);
    cudaGetSymbolAddress((void**)&q, g_q);
    cudaGetSymbolAddress((void**)&k, g_k);
    cudaGetSymbolAddress((void**)&v, g_v);
    cudaGetSymbolAddress((void**)&o, g_o);
    cudaGetSymbolAddress((void**)&s, g_s);

    // 1) GroupNorm -> token layout g_t [B*N, C]
    gn_kernel<<<BATCH * NGROUP, 512>>>(x, gw, gb);

    // 2) Q, K, V projections: [8192,512] x [512,512]^T
    dim3 blk(256);
    dim3 gQKV(CH / 64, NTOK / 64, 1);
    gemm_nt<<<gQKV, blk>>>(t, wq, bq, q, CH, CH, 1.f, 0, 0, 0);
    gemm_nt<<<gQKV, blk>>>(t, wk, bk, k, CH, CH, 1.f, 0, 0, 0);
    gemm_nt<<<gQKV, blk>>>(t, wv, bv, v, CH, CH, 1.f, 0, 0, 0);

    // 3) S = scale * Q K^T   (batched over B)
    dim3 gS(NTOKB / 64, NTOKB / 64, BATCH);
    gemm_nt<<<gS, blk>>>(q, k, nullptr, s, CH, NTOKB, SCALE,
                         (size_t)NTOKB * CH, (size_t)NTOKB * CH,
                         (size_t)NTOKB * NTOKB);

    // 4) row softmax (8192 rows x 4096)
    softmax_kernel<<<NTOK, 256>>>(s);

    // 5) O = A V  (batched over B)
    dim3 gAV(CH / 64, NTOKB / 64, BATCH);
    gemm_nn<<<gAV, blk>>>(s, v, o, NTOKB, CH, CH,
                          (size_t)NTOKB * NTOKB, (size_t)NTOKB * CH,
                          (size_t)NTOKB * CH);

    // 6) out = O wo^T + bo, transpose to [B,C,H,W], + residual
    dim3 gO(CH / 64, NTOK / 64, 1);
    gemm_out<<<gO, blk>>>(o, wo, bo, x, out);
}

// round 6
// speedup vs baseline: 2.3590x; 2.3590x over previous
#include <cuda_runtime.h>

#define BATCH  2
#define CH     512
#define NTOKB  4096              // tokens per batch (H*W)
#define NTOK   (BATCH * NTOKB)   // 8192
#define NGROUP 32
#define CPG    (CH / NGROUP)     // 16
#define EPS    1e-5f
#define SCALE  0.04419417382415922f   // 1/sqrt(512)

// ---------------- scratch (device globals; no allocations allowed) ----------
__device__ float g_t[(size_t)NTOK * CH];                 // normalized tokens [B*N, C]
__device__ float g_q[(size_t)NTOK * CH];
__device__ float g_k[(size_t)NTOK * CH];
__device__ float g_v[(size_t)NTOK * CH];
__device__ float g_o[(size_t)NTOK * CH];
__device__ float g_s[(size_t)BATCH * NTOKB * NTOKB];     // attention scores, 128 MB

// ---------------- tf32 helpers ----------------------------------------------
__device__ __forceinline__ unsigned f2tf32(float x) {
    unsigned r;
    asm("cvt.rna.tf32.f32 %0, %1;" : "=r"(r) : "f"(x));
    return r;
}

__device__ __forceinline__ void mma_tf32(float* d, const unsigned* a, const unsigned* b) {
    asm volatile(
        "mma.sync.aligned.m16n8k8.row.col.f32.tf32.tf32.f32 "
        "{%0,%1,%2,%3}, {%4,%5,%6,%7}, {%8,%9}, {%0,%1,%2,%3};\n"
        : "+f"(d[0]), "+f"(d[1]), "+f"(d[2]), "+f"(d[3])
        : "r"(a[0]), "r"(a[1]), "r"(a[2]), "r"(a[3]), "r"(b[0]), "r"(b[1]));
}

// ---------------- GroupNorm + transpose to [B, N, C] ------------------------
__global__ __launch_bounds__(512) void gn_kernel(
    const float* __restrict__ x, const float* __restrict__ gw,
    const float* __restrict__ gb)
{
    const int b = blockIdx.x >> 5;
    const int g = blockIdx.x & 31;
    const float* xp = x + ((size_t)b * CH + (size_t)g * CPG) * NTOKB;
    const int NEL = CPG * NTOKB;   // 65536

    float s = 0.f, ss = 0.f;
    for (int i = threadIdx.x; i < NEL; i += 512) {
        float v = xp[i]; s += v; ss += v * v;
    }
    __shared__ float rs[16], rss[16], bc[2];
#pragma unroll
    for (int o = 16; o > 0; o >>= 1) {
        s  += __shfl_xor_sync(0xffffffffu, s, o);
        ss += __shfl_xor_sync(0xffffffffu, ss, o);
    }
    if ((threadIdx.x & 31) == 0) { rs[threadIdx.x >> 5] = s; rss[threadIdx.x >> 5] = ss; }
    __syncthreads();
    if (threadIdx.x < 32) {
        s  = (threadIdx.x < 16) ? rs[threadIdx.x]  : 0.f;
        ss = (threadIdx.x < 16) ? rss[threadIdx.x] : 0.f;
#pragma unroll
        for (int o = 8; o > 0; o >>= 1) {
            s  += __shfl_xor_sync(0xffffffffu, s, o);
            ss += __shfl_xor_sync(0xffffffffu, ss, o);
        }
        if (threadIdx.x == 0) {
            float mean = s / (float)NEL;
            float var  = ss / (float)NEL - mean * mean;
            bc[0] = mean;
            bc[1] = rsqrtf(var + EPS);
        }
    }
    __syncthreads();
    const float mean = bc[0], inv = bc[1];
    for (int i = threadIdx.x; i < NEL; i += 512) {
        int cl = i >> 12;           // /4096
        int n  = i & (NTOKB - 1);
        int c  = g * CPG + cl;
        float v = (xp[i] - mean) * inv * gw[c] + gb[c];
        g_t[((size_t)b * NTOKB + n) * CH + c] = v;
    }
}

// ============================================================================
// TF32 tensor-core GEMMs.  Block tile 128x128x16, 256 thr = 8 warps (2m x 4n),
// warp tile 64x32 -> 4x4 grid of m16n8k8 mma fragments.
// Smem tiles k-major [16][132] (tf32 bits); fragment LDS is conflict-free.
// ============================================================================

#define GEMM_MAINLOOP_NT()                                                     \
    const int tid = threadIdx.x;                                               \
    const int lane = tid & 31, w = tid >> 5;                                   \
    const int wm0 = (w >> 2) * 64, wn0 = (w & 3) * 32;                         \
    const int fg = lane >> 2, fq = lane & 3;                                   \
    const int lc = tid & 15, lr = tid >> 4;                                    \
    __shared__ unsigned As[16][132];                                           \
    __shared__ unsigned Bs[16][132];                                           \
    const float* Ap = A + (size_t)(m0 + lr) * K + lc;                          \
    const float* Bp = B + (size_t)(n0 + lr) * K + lc;                          \
    float ar[8], br[8];                                                        \
    _Pragma("unroll")                                                          \
    for (int u = 0; u < 8; u++) {                                              \
        ar[u] = Ap[(size_t)(16 * u) * K];                                      \
        br[u] = Bp[(size_t)(16 * u) * K];                                      \
    }                                                                          \
    float acc[4][4][4] = {};                                                   \
    for (int kt = 0; kt < K; kt += 16) {                                       \
        _Pragma("unroll")                                                      \
        for (int u = 0; u < 8; u++) {                                          \
            As[lc][lr + 16 * u] = f2tf32(ar[u]);                               \
            Bs[lc][lr + 16 * u] = f2tf32(br[u]);                               \
        }                                                                      \
        __syncthreads();                                                       \
        if (kt + 16 < K) {                                                     \
            Ap += 16; Bp += 16;                                                \
            _Pragma("unroll")                                                  \
            for (int u = 0; u < 8; u++) {                                      \
                ar[u] = Ap[(size_t)(16 * u) * K];                              \
                br[u] = Bp[(size_t)(16 * u) * K];                              \
            }                                                                  \
        }                                                                      \
        _Pragma("unroll")                                                      \
        for (int ks = 0; ks < 16; ks += 8) {                                   \
            unsigned bf[4][2];                                                 \
            _Pragma("unroll")                                                  \
            for (int nt = 0; nt < 4; nt++) {                                   \
                bf[nt][0] = Bs[ks + fq][wn0 + nt * 8 + fg];                    \
                bf[nt][1] = Bs[ks + fq + 4][wn0 + nt * 8 + fg];                \
            }                                                                  \
            _Pragma("unroll")                                                  \
            for (int mt = 0; mt < 4; mt++) {                                   \
                unsigned af[4];                                                \
                const int am = wm0 + mt * 16 + fg;                             \
                af[0] = As[ks + fq][am];                                       \
                af[1] = As[ks + fq][am + 8];                                   \
                af[2] = As[ks + fq + 4][am];                                   \
                af[3] = As[ks + fq + 4][am + 8];                               \
                _Pragma("unroll")                                              \
                for (int nt = 0; nt < 4; nt++)                                 \
                    mma_tf32(acc[mt][nt], af, bf[nt]);                         \
            }                                                                  \
        }                                                                      \
        __syncthreads();                                                       \
    }

// ---- NT:  C[m,n] = alpha * sum_k A[m,k] B[n,k] (+ bias[n]) -----------------
__global__ __launch_bounds__(256, 2) void gemm_nt_mma(
    const float* __restrict__ A, const float* __restrict__ B,
    const float* __restrict__ bias, float* __restrict__ Cc,
    int K, int ldc, float alpha,
    size_t aStride, size_t bStride, size_t cStride)
{
    A  += (size_t)blockIdx.z * aStride;
    B  += (size_t)blockIdx.z * bStride;
    Cc += (size_t)blockIdx.z * cStride;
    const int m0 = blockIdx.y * 128;
    const int n0 = blockIdx.x * 128;

    GEMM_MAINLOOP_NT();

#pragma unroll
    for (int nt = 0; nt < 4; nt++) {
        const int col = n0 + wn0 + nt * 8 + 2 * fq;
        const float b0 = bias ? bias[col]     : 0.f;
        const float b1 = bias ? bias[col + 1] : 0.f;
#pragma unroll
        for (int mt = 0; mt < 4; mt++) {
            const int row = m0 + wm0 + mt * 16 + fg;
            float2 v0 = { alpha * acc[mt][nt][0] + b0, alpha * acc[mt][nt][1] + b1 };
            float2 v1 = { alpha * acc[mt][nt][2] + b0, alpha * acc[mt][nt][3] + b1 };
            *(float2*)&Cc[(size_t)row * ldc + col]       = v0;
            *(float2*)&Cc[(size_t)(row + 8) * ldc + col] = v1;
        }
    }
}

// ---- NN:  C[m,n] = sum_k A[m,k] B[k,n]  (A lda=K, B ldb, C ldc) ------------
__global__ __launch_bounds__(256, 2) void gemm_nn_mma(
    const float* __restrict__ A, const float* __restrict__ B,
    float* __restrict__ Cc, int K, int ldb, int ldc,
    size_t aStride, size_t bStride, size_t cStride)
{
    A  += (size_t)blockIdx.z * aStride;
    B  += (size_t)blockIdx.z * bStride;
    Cc += (size_t)blockIdx.z * cStride;
    const int m0 = blockIdx.y * 128;
    const int n0 = blockIdx.x * 128;

    const int tid = threadIdx.x;
    const int lane = tid & 31, w = tid >> 5;
    const int wm0 = (w >> 2) * 64, wn0 = (w & 3) * 32;
    const int fg = lane >> 2, fq = lane & 3;
    const int lc = tid & 15, lr = tid >> 4;
    const int bcol = tid & 127, brow = tid >> 7;   // B loader: [k][n] rows

    __shared__ unsigned As[16][132];
    __shared__ unsigned Bs[16][132];

    const float* Ap = A + (size_t)(m0 + lr) * K + lc;
    const float* Bp = B + (size_t)brow * ldb + n0 + bcol;

    float ar[8], br[8];
#pragma unroll
    for (int u = 0; u < 8; u++) {
        ar[u] = Ap[(size_t)(16 * u) * K];
        br[u] = Bp[(size_t)(2 * u) * ldb];
    }

    float acc[4][4][4] = {};
    for (int kt = 0; kt < K; kt += 16) {
#pragma unroll
        for (int u = 0; u < 8; u++) {
            As[lc][lr + 16 * u] = f2tf32(ar[u]);
            Bs[brow + 2 * u][bcol] = f2tf32(br[u]);
        }
        __syncthreads();
        if (kt + 16 < K) {
            Ap += 16; Bp += (size_t)16 * ldb;
#pragma unroll
            for (int u = 0; u < 8; u++) {
                ar[u] = Ap[(size_t)(16 * u) * K];
                br[u] = Bp[(size_t)(2 * u) * ldb];
            }
        }
#pragma unroll
        for (int ks = 0; ks < 16; ks += 8) {
            unsigned bf[4][2];
#pragma unroll
            for (int nt = 0; nt < 4; nt++) {
                bf[nt][0] = Bs[ks + fq][wn0 + nt * 8 + fg];
                bf[nt][1] = Bs[ks + fq + 4][wn0 + nt * 8 + fg];
            }
#pragma unroll
            for (int mt = 0; mt < 4; mt++) {
                unsigned af[4];
                const int am = wm0 + mt * 16 + fg;
                af[0] = As[ks + fq][am];
                af[1] = As[ks + fq][am + 8];
                af[2] = As[ks + fq + 4][am];
                af[3] = As[ks + fq + 4][am + 8];
#pragma unroll
                for (int nt = 0; nt < 4; nt++)
                    mma_tf32(acc[mt][nt], af, bf[nt]);
            }
        }
        __syncthreads();
    }

#pragma unroll
    for (int nt = 0; nt < 4; nt++) {
        const int col = n0 + wn0 + nt * 8 + 2 * fq;
#pragma unroll
        for (int mt = 0; mt < 4; mt++) {
            const int row = m0 + wm0 + mt * 16 + fg;
            float2 v0 = { acc[mt][nt][0], acc[mt][nt][1] };
            float2 v1 = { acc[mt][nt][2], acc[mt][nt][3] };
            *(float2*)&Cc[(size_t)row * ldc + col]       = v0;
            *(float2*)&Cc[(size_t)(row + 8) * ldc + col] = v1;
        }
    }
}

// ---- out-proj: NT gemm + bias + residual + transpose to [B,C,H,W] ----------
__global__ __launch_bounds__(256, 2) void gemm_out_mma(
    const float* __restrict__ A /* g_o [B*N, C] */, const float* __restrict__ B /* wo */,
    const float* __restrict__ bo, const float* __restrict__ x,
    float* __restrict__ out)
{
    const int K = CH;
    const int m0 = blockIdx.y * 128;
    const int n0 = blockIdx.x * 128;

    GEMM_MAINLOOP_NT();

#pragma unroll
    for (int nt = 0; nt < 4; nt++) {
        const int col = n0 + wn0 + nt * 8 + 2 * fq;
        const float b0 = bo[col];
        const float b1 = bo[col + 1];
#pragma unroll
        for (int mt = 0; mt < 4; mt++) {
#pragma unroll
            for (int half = 0; half < 2; half++) {
                const int row = m0 + wm0 + mt * 16 + fg + 8 * half;  // global token
                const int b = row >> 12;
                const int n = row & (NTOKB - 1);
                const size_t i0 = ((size_t)(b * CH + col)) * NTOKB + n;
                const size_t i1 = i0 + NTOKB;
                out[i0] = acc[mt][nt][2 * half + 0] + b0 + x[i0];
                out[i1] = acc[mt][nt][2 * half + 1] + b1 + x[i1];
            }
        }
    }
}

// ---------------- row softmax over the last axis (4096) ---------------------
__global__ __launch_bounds__(256) void softmax_kernel(float* __restrict__ s)
{
    float* p = s + (size_t)blockIdx.x * NTOKB;
    const int tid = threadIdx.x;
    float v[16];
    float m = -1e30f;
#pragma unroll
    for (int i = 0; i < 16; i++) { v[i] = p[i * 256 + tid]; m = fmaxf(m, v[i]); }

    __shared__ float sh[8], bcv[1];
#pragma unroll
    for (int o = 16; o > 0; o >>= 1) m = fmaxf(m, __shfl_xor_sync(0xffffffffu, m, o));
    if ((tid & 31) == 0) sh[tid >> 5] = m;
    __syncthreads();
    if (tid < 32) {
        float t = (tid < 8) ? sh[tid] : -1e30f;
#pragma unroll
        for (int o = 4; o > 0; o >>= 1) t = fmaxf(t, __shfl_xor_sync(0xffffffffu, t, o));
        if (tid == 0) bcv[0] = t;
    }
    __syncthreads();
    const float M = bcv[0];

    float sum = 0.f;
#pragma unroll
    for (int i = 0; i < 16; i++) { v[i] = __expf(v[i] - M); sum += v[i]; }
    __syncthreads();
#pragma unroll
    for (int o = 16; o > 0; o >>= 1) sum += __shfl_xor_sync(0xffffffffu, sum, o);
    if ((tid & 31) == 0) sh[tid >> 5] = sum;
    __syncthreads();
    if (tid < 32) {
        float t = (tid < 8) ? sh[tid] : 0.f;
#pragma unroll
        for (int o = 4; o > 0; o >>= 1) t += __shfl_xor_sync(0xffffffffu, t, o);
        if (tid == 0) bcv[0] = 1.f / t;
    }
    __syncthreads();
    const float inv = bcv[0];
#pragma unroll
    for (int i = 0; i < 16; i++) p[i * 256 + tid] = v[i] * inv;
}

// ---------------- launch ----------------------------------------------------
extern "C" void kernel_launch(void* const* d_in, const int* in_sizes, int n_in,
                              void* d_out, int out_size)
{
    const float* x  = (const float*)d_in[0];
    const float* gw = (const float*)d_in[1];
    const float* gb = (const float*)d_in[2];
    const float* wq = (const float*)d_in[3];
    const float* bq = (const float*)d_in[4];
    const float* wk = (const float*)d_in[5];
    const float* bk = (const float*)d_in[6];
    const float* wv = (const float*)d_in[7];
    const float* bv = (const float*)d_in[8];
    const float* wo = (const float*)d_in[9];
    const float* bo = (const float*)d_in[10];
    float* out = (float*)d_out;

    float *t, *q, *k, *v, *o, *s;
    cudaGetSymbolAddress((void**)&t, g_t);
    cudaGetSymbolAddress((void**)&q, g_q);
    cudaGetSymbolAddress((void**)&k, g_k);
    cudaGetSymbolAddress((void**)&v, g_v);
    cudaGetSymbolAddress((void**)&o, g_o);
    cudaGetSymbolAddress((void**)&s, g_s);

    // 1) GroupNorm -> token layout g_t [B*N, C]
    gn_kernel<<<BATCH * NGROUP, 512>>>(x, gw, gb);

    // 2) Q, K, V projections: [8192,512] x [512,512]^T
    dim3 blk(256);
    dim3 gQKV(CH / 128, NTOK / 128, 1);
    gemm_nt_mma<<<gQKV, blk>>>(t, wq, bq, q, CH, CH, 1.f, 0, 0, 0);
    gemm_nt_mma<<<gQKV, blk>>>(t, wk, bk, k, CH, CH, 1.f, 0, 0, 0);
    gemm_nt_mma<<<gQKV, blk>>>(t, wv, bv, v, CH, CH, 1.f, 0, 0, 0);

    // 3) S = scale * Q K^T   (batched over B)
    dim3 gS(NTOKB / 128, NTOKB / 128, BATCH);
    gemm_nt_mma<<<gS, blk>>>(q, k, nullptr, s, CH, NTOKB, SCALE,
                             (size_t)NTOKB * CH, (size_t)NTOKB * CH,
                             (size_t)NTOKB * NTOKB);

    // 4) row softmax (8192 rows x 4096)
    softmax_kernel<<<NTOK, 256>>>(s);

    // 5) O = A V  (batched over B)
    dim3 gAV(CH / 128, NTOKB / 128, BATCH);
    gemm_nn_mma<<<gAV, blk>>>(s, v, o, NTOKB, CH, CH,
                              (size_t)NTOKB * NTOKB, (size_t)NTOKB * CH,
                              (size_t)NTOKB * CH);

    // 6) out = O wo^T + bo, transpose to [B,C,H,W], + residual
    dim3 gO(CH / 128, NTOK / 128, 1);
    gemm_out_mma<<<gO, blk>>>(o, wo, bo, x, out);
}

// round 8
// speedup vs baseline: 3.1881x; 1.3515x over previous
#include <cuda_runtime.h>

#define BATCH  2
#define CH     512
#define NTOKB  4096              // tokens per batch (H*W)
#define NTOK   (BATCH * NTOKB)   // 8192
#define NGROUP 32
#define CPG    (CH / NGROUP)     // 16
#define EPS    1e-5f
#define SCALE  0.04419417382415922f   // 1/sqrt(512)

// ---------------- scratch (device globals; no allocations allowed) ----------
__device__ float g_t[(size_t)NTOK * CH];                 // normalized tokens [B*N, C]
__device__ float g_q[(size_t)NTOK * CH];
__device__ float g_k[(size_t)NTOK * CH];
__device__ float g_v[(size_t)NTOK * CH];
__device__ float g_o[(size_t)NTOK * CH];
__device__ float g_s[(size_t)BATCH * NTOKB * NTOKB];     // attention scores, 128 MB

// ---------------- primitives ------------------------------------------------
__device__ __forceinline__ void mma_tf32(float* d, const unsigned* a, const unsigned* b) {
    asm volatile(
        "mma.sync.aligned.m16n8k8.row.col.f32.tf32.tf32.f32 "
        "{%0,%1,%2,%3}, {%4,%5,%6,%7}, {%8,%9}, {%0,%1,%2,%3};\n"
        : "+f"(d[0]), "+f"(d[1]), "+f"(d[2]), "+f"(d[3])
        : "r"(a[0]), "r"(a[1]), "r"(a[2]), "r"(a[3]), "r"(b[0]), "r"(b[1]));
}

__device__ __forceinline__ unsigned sptr(const void* p) {
    return (unsigned)__cvta_generic_to_shared(p);
}
#define CP16(dst, src) asm volatile("cp.async.cg.shared.global [%0], [%1], 16;" :: "r"(dst), "l"(src))
#define CPCOMMIT()     asm volatile("cp.async.commit_group;")
#define CPWAIT1()      asm volatile("cp.async.wait_group 1;")

#define PA 12     // pitch (floats) for [128 x 8] k-major-row tiles; conflict-free
#define PB 136    // pitch (floats) for [8 x 128] n-rows tiles (NN B); conflict-free

struct NTSm { float A[3][128][PA]; float B[3][128][PA]; };      // 36,864 B
struct NNSm { float A[3][128][PA]; float B[3][8][PB];   };      // 31,488 B

// load a [128 rows x 8 floats] tile, rows stride ld (src pre-offset to (row0, k0))
__device__ __forceinline__ void load_t128x8(float (*dst)[PA], const float* src, int ld, int tid) {
#pragma unroll
    for (int i = 0; i < 2; i++) {
        int chunk = i * 128 + tid;
        int row = chunk >> 1, seg = chunk & 1;
        CP16(sptr(&dst[row][seg * 4]), src + (size_t)row * ld + seg * 4);
    }
}
// load an [8 rows x 128 floats] tile, rows stride ld (src pre-offset to (k0, n0))
__device__ __forceinline__ void load_t8x128(float (*dst)[PB], const float* src, int ld, int tid) {
#pragma unroll
    for (int i = 0; i < 2; i++) {
        int chunk = i * 128 + tid;
        int row = chunk >> 5, c4 = chunk & 31;
        CP16(sptr(&dst[row][c4 * 4]), src + (size_t)row * ld + c4 * 4);
    }
}

// ---------------- NT mainloop: C[128,128] += A[m0+.,k] * B[n0+.,k] ----------
// 128 threads, 4 warps (2m x 2n), warp tile 64x64 = 4x8 m16n8k8 fragments.
__device__ __forceinline__ void nt_main(const float* A, const float* B, int K,
                                        NTSm* sm, float acc[4][8][4], int m0, int n0)
{
    const int tid = threadIdx.x;
    const int lane = tid & 31, w = tid >> 5;
    const int wm0 = (w >> 1) * 64, wn0 = (w & 1) * 64;
    const int fg = lane >> 2, fq = lane & 3;

    const float* Ab = A + (size_t)m0 * K;
    const float* Bb = B + (size_t)n0 * K;

    load_t128x8(sm->A[0], Ab, K, tid);
    load_t128x8(sm->B[0], Bb, K, tid);
    CPCOMMIT();
    load_t128x8(sm->A[1], Ab + 8, K, tid);
    load_t128x8(sm->B[1], Bb + 8, K, tid);
    CPCOMMIT();

    const int NK = K >> 3;
    int cur = 0, nxt = 2;
    for (int it = 0; it < NK; ++it) {
        CPWAIT1();
        __syncthreads();
        if (it + 2 < NK) {
            load_t128x8(sm->A[nxt], Ab + (it + 2) * 8, K, tid);
            load_t128x8(sm->B[nxt], Bb + (it + 2) * 8, K, tid);
        }
        CPCOMMIT();

        const unsigned (*As)[PA] = reinterpret_cast<const unsigned(*)[PA]>(sm->A[cur]);
        const unsigned (*Bs)[PA] = reinterpret_cast<const unsigned(*)[PA]>(sm->B[cur]);
        unsigned bf[8][2];
#pragma unroll
        for (int nt = 0; nt < 8; nt++) {
            bf[nt][0] = Bs[wn0 + nt * 8 + fg][fq];
            bf[nt][1] = Bs[wn0 + nt * 8 + fg][fq + 4];
        }
#pragma unroll
        for (int mt = 0; mt < 4; mt++) {
            unsigned af[4];
            const int am = wm0 + mt * 16 + fg;
            af[0] = As[am][fq];     af[1] = As[am + 8][fq];
            af[2] = As[am][fq + 4]; af[3] = As[am + 8][fq + 4];
#pragma unroll
            for (int nt = 0; nt < 8; nt++)
                mma_tf32(acc[mt][nt], af, bf[nt]);
        }
        cur = (cur == 2) ? 0 : cur + 1;
        nxt = (nxt == 2) ? 0 : nxt + 1;
    }
}

// ---------------- NN mainloop: C[128,128] += A[m0+.,k] * B[k, n0+.] ---------
__device__ __forceinline__ void nn_main(const float* A, const float* B, int K, int ldb,
                                        NNSm* sm, float acc[4][8][4], int m0, int n0)
{
    const int tid = threadIdx.x;
    const int lane = tid & 31, w = tid >> 5;
    const int wm0 = (w >> 1) * 64, wn0 = (w & 1) * 64;
    const int fg = lane >> 2, fq = lane & 3;

    const float* Ab = A + (size_t)m0 * K;
    const float* Bb = B + n0;

    load_t128x8(sm->A[0], Ab, K, tid);
    load_t8x128(sm->B[0], Bb, ldb, tid);
    CPCOMMIT();
    load_t128x8(sm->A[1], Ab + 8, K, tid);
    load_t8x128(sm->B[1], Bb + (size_t)8 * ldb, ldb, tid);
    CPCOMMIT();

    const int NK = K >> 3;
    int cur = 0, nxt = 2;
    for (int it = 0; it < NK; ++it) {
        CPWAIT1();
        __syncthreads();
        if (it + 2 < NK) {
            load_t128x8(sm->A[nxt], Ab + (it + 2) * 8, K, tid);
            load_t8x128(sm->B[nxt], Bb + (size_t)(it + 2) * 8 * ldb, ldb, tid);
        }
        CPCOMMIT();

        const unsigned (*As)[PA] = reinterpret_cast<const unsigned(*)[PA]>(sm->A[cur]);
        const unsigned (*Bs)[PB] = reinterpret_cast<const unsigned(*)[PB]>(sm->B[cur]);
        unsigned bf[8][2];
#pragma unroll
        for (int nt = 0; nt < 8; nt++) {
            bf[nt][0] = Bs[fq][wn0 + nt * 8 + fg];
            bf[nt][1] = Bs[fq + 4][wn0 + nt * 8 + fg];
        }
#pragma unroll
        for (int mt = 0; mt < 4; mt++) {
            unsigned af[4];
            const int am = wm0 + mt * 16 + fg;
            af[0] = As[am][fq];     af[1] = As[am + 8][fq];
            af[2] = As[am][fq + 4]; af[3] = As[am + 8][fq + 4];
#pragma unroll
            for (int nt = 0; nt < 8; nt++)
                mma_tf32(acc[mt][nt], af, bf[nt]);
        }
        cur = (cur == 2) ? 0 : cur + 1;
        nxt = (nxt == 2) ? 0 : nxt + 1;
    }
}

// ---------------- standard epilogue -----------------------------------------
__device__ __forceinline__ void nt_epi(float acc[4][8][4], const float* bias,
                                       float* Cc, int ldc, float alpha, int m0, int n0)
{
    const int tid = threadIdx.x, lane = tid & 31, w = tid >> 5;
    const int wm0 = (w >> 1) * 64, wn0 = (w & 1) * 64;
    const int fg = lane >> 2, fq = lane & 3;
#pragma unroll
    for (int nt = 0; nt < 8; nt++) {
        const int col = n0 + wn0 + nt * 8 + 2 * fq;
        const float b0 = bias ? bias[col]     : 0.f;
        const float b1 = bias ? bias[col + 1] : 0.f;
#pragma unroll
        for (int mt = 0; mt < 4; mt++) {
            const int row = m0 + wm0 + mt * 16 + fg;
            float2 v0 = { alpha * acc[mt][nt][0] + b0, alpha * acc[mt][nt][1] + b1 };
            float2 v1 = { alpha * acc[mt][nt][2] + b0, alpha * acc[mt][nt][3] + b1 };
            *(float2*)&Cc[(size_t)row * ldc + col]       = v0;
            *(float2*)&Cc[(size_t)(row + 8) * ldc + col] = v1;
        }
    }
}

// ---------------- kernels ---------------------------------------------------
__global__ __launch_bounds__(128) void gemm_qkv(
    const float* __restrict__ t,
    const float* __restrict__ wq, const float* __restrict__ bq, float* __restrict__ q,
    const float* __restrict__ wk, const float* __restrict__ bk, float* __restrict__ k,
    const float* __restrict__ wv, const float* __restrict__ bv, float* __restrict__ v)
{
    __shared__ NTSm sm;
    const float* W  = blockIdx.z == 0 ? wq : blockIdx.z == 1 ? wk : wv;
    const float* bs = blockIdx.z == 0 ? bq : blockIdx.z == 1 ? bk : bv;
    float*       C  = blockIdx.z == 0 ? q  : blockIdx.z == 1 ? k  : v;
    float acc[4][8][4] = {};
    nt_main(t, W, CH, &sm, acc, blockIdx.y * 128, blockIdx.x * 128);
    nt_epi(acc, bs, C, CH, 1.f, blockIdx.y * 128, blockIdx.x * 128);
}

__global__ __launch_bounds__(128) void gemm_s(
    const float* __restrict__ q, const float* __restrict__ k, float* __restrict__ s)
{
    __shared__ NTSm sm;
    const size_t zo = (size_t)blockIdx.z * NTOKB * CH;
    float acc[4][8][4] = {};
    nt_main(q + zo, k + zo, CH, &sm, acc, blockIdx.y * 128, blockIdx.x * 128);
    nt_epi(acc, nullptr, s + (size_t)blockIdx.z * NTOKB * NTOKB, NTOKB, SCALE,
           blockIdx.y * 128, blockIdx.x * 128);
}

__global__ __launch_bounds__(128) void gemm_av(
    const float* __restrict__ s, const float* __restrict__ v, float* __restrict__ o)
{
    __shared__ NNSm sm;
    float acc[4][8][4] = {};
    nn_main(s + (size_t)blockIdx.z * NTOKB * NTOKB, v + (size_t)blockIdx.z * NTOKB * CH,
            NTOKB, CH, &sm, acc, blockIdx.y * 128, blockIdx.x * 128);
    nt_epi(acc, nullptr, o + (size_t)blockIdx.z * NTOKB * CH, CH, 1.f,
           blockIdx.y * 128, blockIdx.x * 128);
}

__global__ __launch_bounds__(128) void gemm_out_k(
    const float* __restrict__ o, const float* __restrict__ wo,
    const float* __restrict__ bo, const float* __restrict__ x, float* __restrict__ out)
{
    __shared__ NTSm sm;
    const int m0 = blockIdx.y * 128, n0 = blockIdx.x * 128;
    float acc[4][8][4] = {};
    nt_main(o, wo, CH, &sm, acc, m0, n0);

    const int tid = threadIdx.x, lane = tid & 31, w = tid >> 5;
    const int wm0 = (w >> 1) * 64, wn0 = (w & 1) * 64;
    const int fg = lane >> 2, fq = lane & 3;
#pragma unroll
    for (int nt = 0; nt < 8; nt++) {
        const int col = n0 + wn0 + nt * 8 + 2 * fq;
        const float b0 = bo[col];
        const float b1 = bo[col + 1];
#pragma unroll
        for (int mt = 0; mt < 4; mt++) {
#pragma unroll
            for (int half = 0; half < 2; half++) {
                const int row = m0 + wm0 + mt * 16 + fg + 8 * half;  // global token
                const int b = row >> 12;
                const int n = row & (NTOKB - 1);
                const size_t i0 = ((size_t)(b * CH + col)) * NTOKB + n;
                const size_t i1 = i0 + NTOKB;
                out[i0] = acc[mt][nt][2 * half + 0] + b0 + x[i0];
                out[i1] = acc[mt][nt][2 * half + 1] + b1 + x[i1];
            }
        }
    }
}

// ---------------- GroupNorm + coalesced transpose to [B, N, C] --------------
__global__ __launch_bounds__(512) void gn_kernel(
    const float* __restrict__ x, const float* __restrict__ gw,
    const float* __restrict__ gb)
{
    const int b = blockIdx.x >> 5;
    const int g = blockIdx.x & 31;
    const float* xp = x + ((size_t)(b * CH + g * CPG)) * NTOKB;

    float s = 0.f, ss = 0.f;
    const float4* xp4 = (const float4*)xp;
    for (int i = threadIdx.x; i < CPG * NTOKB / 4; i += 512) {
        float4 vv = xp4[i];
        s  += vv.x + vv.y + vv.z + vv.w;
        ss += vv.x * vv.x + vv.y * vv.y + vv.z * vv.z + vv.w * vv.w;
    }
    __shared__ float rs[16], rss[16], bc[2];
#pragma unroll
    for (int o = 16; o > 0; o >>= 1) {
        s  += __shfl_xor_sync(0xffffffffu, s, o);
        ss += __shfl_xor_sync(0xffffffffu, ss, o);
    }
    if ((threadIdx.x & 31) == 0) { rs[threadIdx.x >> 5] = s; rss[threadIdx.x >> 5] = ss; }
    __syncthreads();
    if (threadIdx.x < 32) {
        s  = (threadIdx.x < 16) ? rs[threadIdx.x]  : 0.f;
        ss = (threadIdx.x < 16) ? rss[threadIdx.x] : 0.f;
#pragma unroll
        for (int o = 8; o > 0; o >>= 1) {
            s  += __shfl_xor_sync(0xffffffffu, s, o);
            ss += __shfl_xor_sync(0xffffffffu, ss, o);
        }
        if (threadIdx.x == 0) {
            const float NEL = (float)(CPG * NTOKB);
            float mean = s / NEL;
            float var  = ss / NEL - mean * mean;
            bc[0] = mean;
            bc[1] = rsqrtf(var + EPS);
        }
    }
    __syncthreads();
    __shared__ float sa[CPG], sb2[CPG];
    if (threadIdx.x < CPG) {
        float a = bc[1] * gw[g * CPG + threadIdx.x];
        sa[threadIdx.x]  = a;
        sb2[threadIdx.x] = gb[g * CPG + threadIdx.x] - bc[0] * a;
    }
    __syncthreads();

    __shared__ float tile[CPG][132];
    const int c  = threadIdx.x >> 5, seg = threadIdx.x & 31;
    const int nl = threadIdx.x >> 2, cq  = threadIdx.x & 3;
    for (int t0 = 0; t0 < NTOKB; t0 += 128) {
        float4 vv = *(const float4*)(xp + (size_t)c * NTOKB + t0 + seg * 4);
        const float a = sa[c], bb = sb2[c];
        tile[c][seg * 4 + 0] = vv.x * a + bb;
        tile[c][seg * 4 + 1] = vv.y * a + bb;
        tile[c][seg * 4 + 2] = vv.z * a + bb;
        tile[c][seg * 4 + 3] = vv.w * a + bb;
        __syncthreads();
        float4 wv;
        wv.x = tile[cq * 4 + 0][nl];
        wv.y = tile[cq * 4 + 1][nl];
        wv.z = tile[cq * 4 + 2][nl];
        wv.w = tile[cq * 4 + 3][nl];
        *(float4*)(g_t + ((size_t)(b * NTOKB + t0 + nl)) * CH + g * CPG + cq * 4) = wv;
        __syncthreads();
    }
}

// ---------------- row softmax over the last axis (4096) ---------------------
__global__ __launch_bounds__(256) void softmax_kernel(float* __restrict__ s)
{
    float4* p4 = (float4*)(s + (size_t)blockIdx.x * NTOKB);
    const int tid = threadIdx.x;
    float4 v[4];
    float m = -1e30f;
#pragma unroll
    for (int i = 0; i < 4; i++) {
        v[i] = p4[i * 256 + tid];
        m = fmaxf(m, fmaxf(fmaxf(v[i].x, v[i].y), fmaxf(v[i].z, v[i].w)));
    }

    __shared__ float sh[8], bcv[1];
#pragma unroll
    for (int o = 16; o > 0; o >>= 1) m = fmaxf(m, __shfl_xor_sync(0xffffffffu, m, o));
    if ((tid & 31) == 0) sh[tid >> 5] = m;
    __syncthreads();
    if (tid < 32) {
        float t = (tid < 8) ? sh[tid] : -1e30f;
#pragma unroll
        for (int o = 4; o > 0; o >>= 1) t = fmaxf(t, __shfl_xor_sync(0xffffffffu, t, o));
        if (tid == 0) bcv[0] = t;
    }
    __syncthreads();
    const float M = bcv[0];

    float sum = 0.f;
#pragma unroll
    for (int i = 0; i < 4; i++) {
        v[i].x = __expf(v[i].x - M); v[i].y = __expf(v[i].y - M);
        v[i].z = __expf(v[i].z - M); v[i].w = __expf(v[i].w - M);
        sum += v[i].x + v[i].y + v[i].z + v[i].w;
    }
    __syncthreads();
#pragma unroll
    for (int o = 16; o > 0; o >>= 1) sum += __shfl_xor_sync(0xffffffffu, sum, o);
    if ((tid & 31) == 0) sh[tid >> 5] = sum;
    __syncthreads();
    if (tid < 32) {
        float t = (tid < 8) ? sh[tid] : 0.f;
#pragma unroll
        for (int o = 4; o > 0; o >>= 1) t += __shfl_xor_sync(0xffffffffu, t, o);
        if (tid == 0) bcv[0] = 1.f / t;
    }
    __syncthreads();
    const float inv = bcv[0];
#pragma unroll
    for (int i = 0; i < 4; i++) {
        v[i].x *= inv; v[i].y *= inv; v[i].z *= inv; v[i].w *= inv;
        p4[i * 256 + tid] = v[i];
    }
}

// ---------------- launch ----------------------------------------------------
extern "C" void kernel_launch(void* const* d_in, const int* in_sizes, int n_in,
                              void* d_out, int out_size)
{
    const float* x  = (const float*)d_in[0];
    const float* gw = (const float*)d_in[1];
    const float* gb = (const float*)d_in[2];
    const float* wq = (const float*)d_in[3];
    const float* bq = (const float*)d_in[4];
    const float* wk = (const float*)d_in[5];
    const float* bk = (const float*)d_in[6];
    const float* wv = (const float*)d_in[7];
    const float* bv = (const float*)d_in[8];
    const float* wo = (const float*)d_in[9];
    const float* bo = (const float*)d_in[10];
    float* out = (float*)d_out;

    float *t, *q, *k, *v, *o, *s;
    cudaGetSymbolAddress((void**)&t, g_t);
    cudaGetSymbolAddress((void**)&q, g_q);
    cudaGetSymbolAddress((void**)&k, g_k);
    cudaGetSymbolAddress((void**)&v, g_v);
    cudaGetSymbolAddress((void**)&o, g_o);
    cudaGetSymbolAddress((void**)&s, g_s);

    // 1) GroupNorm -> token layout g_t [B*N, C]
    gn_kernel<<<BATCH * NGROUP, 512>>>(x, gw, gb);

    // 2) fused Q/K/V projections: [8192,512] x [512,512]^T, z picks the head
    gemm_qkv<<<dim3(CH / 128, NTOK / 128, 3), 128>>>(t, wq, bq, q, wk, bk, k, wv, bv, v);

    // 3) S = scale * Q K^T  (batched over B)
    gemm_s<<<dim3(NTOKB / 128, NTOKB / 128, BATCH), 128>>>(q, k, s);

    // 4) row softmax (8192 rows x 4096)
    softmax_kernel<<<NTOK, 256>>>(s);

    // 5) O = A V  (batched over B)
    gemm_av<<<dim3(CH / 128, NTOKB / 128, BATCH), 128>>>(s, v, o);

    // 6) out = O wo^T + bo, transpose to [B,C,H,W], + residual
    gemm_out_k<<<dim3(CH / 128, NTOK / 128, 1), 128>>>(o, wo, bo, x, out);
}

// round 10
// speedup vs baseline: 3.8988x; 1.2229x over previous
#include <cuda_runtime.h>

#define BATCH  2
#define CH     512
#define NTOKB  4096              // tokens per batch (H*W)
#define NTOK   (BATCH * NTOKB)   // 8192
#define NGROUP 32
#define CPG    (CH / NGROUP)     // 16
#define EPS    1e-5f
#define SCALE  0.04419417382415922f   // 1/sqrt(512)

// ---------------- scratch (device globals; no allocations allowed) ----------
__device__ float g_t[(size_t)NTOK * CH];                 // normalized tokens [B*N, C]
__device__ float g_q[(size_t)NTOK * CH];
__device__ float g_k[(size_t)NTOK * CH];
__device__ float g_v[(size_t)NTOK * CH];
__device__ float g_o[(size_t)NTOK * CH];
__device__ float g_s[(size_t)BATCH * NTOKB * NTOKB];     // exp(scores), 128 MB
__device__ float g_rowsum[NTOK];                          // softmax denominators

// ---------------- primitives ------------------------------------------------
__device__ __forceinline__ void mma_tf32(float* d, const unsigned* a, const unsigned* b) {
    asm volatile(
        "mma.sync.aligned.m16n8k8.row.col.f32.tf32.tf32.f32 "
        "{%0,%1,%2,%3}, {%4,%5,%6,%7}, {%8,%9}, {%0,%1,%2,%3};\n"
        : "+f"(d[0]), "+f"(d[1]), "+f"(d[2]), "+f"(d[3])
        : "r"(a[0]), "r"(a[1]), "r"(a[2]), "r"(a[3]), "r"(b[0]), "r"(b[1]));
}

__device__ __forceinline__ unsigned sptr(const void* p) {
    return (unsigned)__cvta_generic_to_shared(p);
}
#define CP16(dst, src) asm volatile("cp.async.cg.shared.global [%0], [%1], 16;" :: "r"(dst), "l"(src))
#define CPCOMMIT()     asm volatile("cp.async.commit_group;")
#define CPWAIT1()      asm volatile("cp.async.wait_group 1;")

#define PA 20     // pitch (floats) for [128 x 16] k-major tiles; conflict-free
#define PB 136    // pitch (floats) for [16 x 128] tiles (NN B); conflict-free

struct NTSm { float A[3][128][PA]; float B[3][128][PA]; };   // 61,440 B (dynamic)
struct NNSm { float A[3][128][PA]; float B[3][16][PB];   };  // 56,832 B (dynamic)

// [128 rows x 16 floats] tile, rows stride ld (src pre-offset to (row0, k0))
__device__ __forceinline__ void load_t128x16(float (*dst)[PA], const float* src, int ld, int tid) {
#pragma unroll
    for (int i = 0; i < 4; i++) {
        int chunk = i * 128 + tid;
        int row = chunk >> 2, seg = chunk & 3;
        CP16(sptr(&dst[row][seg * 4]), src + (size_t)row * ld + seg * 4);
    }
}
// [16 rows x 128 floats] tile, rows stride ld (src pre-offset to (k0, n0))
__device__ __forceinline__ void load_t16x128(float (*dst)[PB], const float* src, int ld, int tid) {
#pragma unroll
    for (int i = 0; i < 4; i++) {
        int chunk = i * 128 + tid;
        int row = chunk >> 5, c4 = chunk & 31;
        CP16(sptr(&dst[row][c4 * 4]), src + (size_t)row * ld + c4 * 4);
    }
}

// ---------------- NT mainloop: C[128,128] += A[m0+.,k] * B[n0+.,k] ----------
// 128 threads, 4 warps (2m x 2n), warp tile 64x64 = 4x8 m16n8k8 fragments.
__device__ __forceinline__ void nt_main(const float* A, const float* B, int K,
                                        NTSm* sm, float acc[4][8][4], int m0, int n0)
{
    const int tid = threadIdx.x;
    const int lane = tid & 31, w = tid >> 5;
    const int wm0 = (w >> 1) * 64, wn0 = (w & 1) * 64;
    const int fg = lane >> 2, fq = lane & 3;

    const float* Ab = A + (size_t)m0 * K;
    const float* Bb = B + (size_t)n0 * K;

    load_t128x16(sm->A[0], Ab, K, tid);
    load_t128x16(sm->B[0], Bb, K, tid);
    CPCOMMIT();
    load_t128x16(sm->A[1], Ab + 16, K, tid);
    load_t128x16(sm->B[1], Bb + 16, K, tid);
    CPCOMMIT();

    const int NK = K >> 4;
    int cur = 0, nxt = 2;
    for (int it = 0; it < NK; ++it) {
        CPWAIT1();
        __syncthreads();
        if (it + 2 < NK) {
            load_t128x16(sm->A[nxt], Ab + (it + 2) * 16, K, tid);
            load_t128x16(sm->B[nxt], Bb + (it + 2) * 16, K, tid);
        }
        CPCOMMIT();

        const unsigned (*As)[PA] = reinterpret_cast<const unsigned(*)[PA]>(sm->A[cur]);
        const unsigned (*Bs)[PA] = reinterpret_cast<const unsigned(*)[PA]>(sm->B[cur]);
#pragma unroll
        for (int ks = 0; ks < 16; ks += 8) {
            unsigned bf[8][2];
#pragma unroll
            for (int nt = 0; nt < 8; nt++) {
                bf[nt][0] = Bs[wn0 + nt * 8 + fg][ks + fq];
                bf[nt][1] = Bs[wn0 + nt * 8 + fg][ks + fq + 4];
            }
#pragma unroll
            for (int mt = 0; mt < 4; mt++) {
                unsigned af[4];
                const int am = wm0 + mt * 16 + fg;
                af[0] = As[am][ks + fq];     af[1] = As[am + 8][ks + fq];
                af[2] = As[am][ks + fq + 4]; af[3] = As[am + 8][ks + fq + 4];
#pragma unroll
                for (int nt = 0; nt < 8; nt++)
                    mma_tf32(acc[mt][nt], af, bf[nt]);
            }
        }
        cur = (cur == 2) ? 0 : cur + 1;
        nxt = (nxt == 2) ? 0 : nxt + 1;
    }
}

// ---------------- NN mainloop: C[128,128] += A[m0+.,k] * B[k, n0+.] ---------
__device__ __forceinline__ void nn_main(const float* A, const float* B, int K, int ldb,
                                        NNSm* sm, float acc[4][8][4], int m0, int n0)
{
    const int tid = threadIdx.x;
    const int lane = tid & 31, w = tid >> 5;
    const int wm0 = (w >> 1) * 64, wn0 = (w & 1) * 64;
    const int fg = lane >> 2, fq = lane & 3;

    const float* Ab = A + (size_t)m0 * K;
    const float* Bb = B + n0;

    load_t128x16(sm->A[0], Ab, K, tid);
    load_t16x128(sm->B[0], Bb, ldb, tid);
    CPCOMMIT();
    load_t128x16(sm->A[1], Ab + 16, K, tid);
    load_t16x128(sm->B[1], Bb + (size_t)16 * ldb, ldb, tid);
    CPCOMMIT();

    const int NK = K >> 4;
    int cur = 0, nxt = 2;
    for (int it = 0; it < NK; ++it) {
        CPWAIT1();
        __syncthreads();
        if (it + 2 < NK) {
            load_t128x16(sm->A[nxt], Ab + (it + 2) * 16, K, tid);
            load_t16x128(sm->B[nxt], Bb + (size_t)(it + 2) * 16 * ldb, ldb, tid);
        }
        CPCOMMIT();

        const unsigned (*As)[PA] = reinterpret_cast<const unsigned(*)[PA]>(sm->A[cur]);
        const unsigned (*Bs)[PB] = reinterpret_cast<const unsigned(*)[PB]>(sm->B[cur]);
#pragma unroll
        for (int ks = 0; ks < 16; ks += 8) {
            unsigned bf[8][2];
#pragma unroll
            for (int nt = 0; nt < 8; nt++) {
                bf[nt][0] = Bs[ks + fq][wn0 + nt * 8 + fg];
                bf[nt][1] = Bs[ks + fq + 4][wn0 + nt * 8 + fg];
            }
#pragma unroll
            for (int mt = 0; mt < 4; mt++) {
                unsigned af[4];
                const int am = wm0 + mt * 16 + fg;
                af[0] = As[am][ks + fq];     af[1] = As[am + 8][ks + fq];
                af[2] = As[am][ks + fq + 4]; af[3] = As[am + 8][ks + fq + 4];
#pragma unroll
                for (int nt = 0; nt < 8; nt++)
                    mma_tf32(acc[mt][nt], af, bf[nt]);
            }
        }
        cur = (cur == 2) ? 0 : cur + 1;
        nxt = (nxt == 2) ? 0 : nxt + 1;
    }
}

// ---------------- standard epilogue -----------------------------------------
__device__ __forceinline__ void nt_epi(float acc[4][8][4], const float* bias,
                                       float* Cc, int ldc, int m0, int n0)
{
    const int tid = threadIdx.x, lane = tid & 31, w = tid >> 5;
    const int wm0 = (w >> 1) * 64, wn0 = (w & 1) * 64;
    const int fg = lane >> 2, fq = lane & 3;
#pragma unroll
    for (int nt = 0; nt < 8; nt++) {
        const int col = n0 + wn0 + nt * 8 + 2 * fq;
        const float b0 = bias ? bias[col]     : 0.f;
        const float b1 = bias ? bias[col + 1] : 0.f;
#pragma unroll
        for (int mt = 0; mt < 4; mt++) {
            const int row = m0 + wm0 + mt * 16 + fg;
            float2 v0 = { acc[mt][nt][0] + b0, acc[mt][nt][1] + b1 };
            float2 v1 = { acc[mt][nt][2] + b0, acc[mt][nt][3] + b1 };
            *(float2*)&Cc[(size_t)row * ldc + col]       = v0;
            *(float2*)&Cc[(size_t)(row + 8) * ldc + col] = v1;
        }
    }
}

// ---------------- kernels ---------------------------------------------------
__global__ __launch_bounds__(128) void gemm_qkv(
    const float* __restrict__ t,
    const float* __restrict__ wq, const float* __restrict__ bq, float* __restrict__ q,
    const float* __restrict__ wk, const float* __restrict__ bk, float* __restrict__ k,
    const float* __restrict__ wv, const float* __restrict__ bv, float* __restrict__ v)
{
    extern __shared__ char dynsm[];
    NTSm* sm = (NTSm*)dynsm;
    const float* W  = blockIdx.z == 0 ? wq : blockIdx.z == 1 ? wk : wv;
    const float* bs = blockIdx.z == 0 ? bq : blockIdx.z == 1 ? bk : bv;
    float*       C  = blockIdx.z == 0 ? q  : blockIdx.z == 1 ? k  : v;
    float acc[4][8][4] = {};
    nt_main(t, W, CH, sm, acc, blockIdx.y * 128, blockIdx.x * 128);
    nt_epi(acc, bs, C, CH, blockIdx.y * 128, blockIdx.x * 128);
}

// S-gemm: writes exp(scale * q.k) and accumulates row sums (no-max softmax).
__global__ __launch_bounds__(128) void gemm_s(
    const float* __restrict__ q, const float* __restrict__ k, float* __restrict__ s)
{
    extern __shared__ char dynsm[];
    NTSm* sm = (NTSm*)dynsm;
    const size_t zo = (size_t)blockIdx.z * NTOKB * CH;
    const int m0 = blockIdx.y * 128, n0 = blockIdx.x * 128;
    float acc[4][8][4] = {};
    nt_main(q + zo, k + zo, CH, sm, acc, m0, n0);

    float* S = s + (size_t)blockIdx.z * NTOKB * NTOKB;
    const int tid = threadIdx.x, lane = tid & 31, w = tid >> 5;
    const int wm0 = (w >> 1) * 64, wn0 = (w & 1) * 64;
    const int fg = lane >> 2, fq = lane & 3;

    float rsum[4][2] = {};
#pragma unroll
    for (int nt = 0; nt < 8; nt++) {
        const int col = n0 + wn0 + nt * 8 + 2 * fq;
#pragma unroll
        for (int mt = 0; mt < 4; mt++) {
            const int row = m0 + wm0 + mt * 16 + fg;
            float e0 = __expf(SCALE * acc[mt][nt][0]);
            float e1 = __expf(SCALE * acc[mt][nt][1]);
            float e2 = __expf(SCALE * acc[mt][nt][2]);
            float e3 = __expf(SCALE * acc[mt][nt][3]);
            float2 v0 = { e0, e1 }, v1 = { e2, e3 };
            *(float2*)&S[(size_t)row * NTOKB + col]       = v0;
            *(float2*)&S[(size_t)(row + 8) * NTOKB + col] = v1;
            rsum[mt][0] += e0 + e1;
            rsum[mt][1] += e2 + e3;
        }
    }
    // reduce over fq lanes (lane ^1, ^2 share fg), then atomically add per row
    const int rbase = blockIdx.z * NTOKB + m0 + wm0;
#pragma unroll
    for (int mt = 0; mt < 4; mt++) {
#pragma unroll
        for (int half = 0; half < 2; half++) {
            float vv = rsum[mt][half];
            vv += __shfl_xor_sync(0xffffffffu, vv, 1);
            vv += __shfl_xor_sync(0xffffffffu, vv, 2);
            if (fq == 0)
                atomicAdd(&g_rowsum[rbase + mt * 16 + fg + 8 * half], vv);
        }
    }
}

// AV-gemm: O = (exp(S) @ V) scaled per row by 1/rowsum.
__global__ __launch_bounds__(128) void gemm_av(
    const float* __restrict__ s, const float* __restrict__ v, float* __restrict__ o)
{
    extern __shared__ char dynsm[];
    NNSm* sm = (NNSm*)dynsm;
    const int m0 = blockIdx.y * 128, n0 = blockIdx.x * 128;
    float acc[4][8][4] = {};
    nn_main(s + (size_t)blockIdx.z * NTOKB * NTOKB, v + (size_t)blockIdx.z * NTOKB * CH,
            NTOKB, CH, sm, acc, m0, n0);

    float* O = o + (size_t)blockIdx.z * NTOKB * CH;
    const int tid = threadIdx.x, lane = tid & 31, w = tid >> 5;
    const int wm0 = (w >> 1) * 64, wn0 = (w & 1) * 64;
    const int fg = lane >> 2, fq = lane & 3;

    const int rbase = blockIdx.z * NTOKB + m0 + wm0;
    float inv[4][2];
#pragma unroll
    for (int mt = 0; mt < 4; mt++) {
        inv[mt][0] = 1.f / g_rowsum[rbase + mt * 16 + fg];
        inv[mt][1] = 1.f / g_rowsum[rbase + mt * 16 + fg + 8];
    }
#pragma unroll
    for (int nt = 0; nt < 8; nt++) {
        const int col = n0 + wn0 + nt * 8 + 2 * fq;
#pragma unroll
        for (int mt = 0; mt < 4; mt++) {
            const int row = m0 + wm0 + mt * 16 + fg;
            float2 v0 = { acc[mt][nt][0] * inv[mt][0], acc[mt][nt][1] * inv[mt][0] };
            float2 v1 = { acc[mt][nt][2] * inv[mt][1], acc[mt][nt][3] * inv[mt][1] };
            *(float2*)&O[(size_t)row * CH + col]       = v0;
            *(float2*)&O[(size_t)(row + 8) * CH + col] = v1;
        }
    }
}

__global__ __launch_bounds__(128) void gemm_out_k(
    const float* __restrict__ o, const float* __restrict__ wo,
    const float* __restrict__ bo, const float* __restrict__ x, float* __restrict__ out)
{
    extern __shared__ char dynsm[];
    NTSm* sm = (NTSm*)dynsm;
    const int m0 = blockIdx.y * 128, n0 = blockIdx.x * 128;
    float acc[4][8][4] = {};
    nt_main(o, wo, CH, sm, acc, m0, n0);

    const int tid = threadIdx.x, lane = tid & 31, w = tid >> 5;
    const int wm0 = (w >> 1) * 64, wn0 = (w & 1) * 64;
    const int fg = lane >> 2, fq = lane & 3;
#pragma unroll
    for (int nt = 0; nt < 8; nt++) {
        const int col = n0 + wn0 + nt * 8 + 2 * fq;
        const float b0 = bo[col];
        const float b1 = bo[col + 1];
#pragma unroll
        for (int mt = 0; mt < 4; mt++) {
#pragma unroll
            for (int half = 0; half < 2; half++) {
                const int row = m0 + wm0 + mt * 16 + fg + 8 * half;  // global token
                const int b = row >> 12;
                const int n = row & (NTOKB - 1);
                const size_t i0 = ((size_t)(b * CH + col)) * NTOKB + n;
                const size_t i1 = i0 + NTOKB;
                out[i0] = acc[mt][nt][2 * half + 0] + b0 + x[i0];
                out[i1] = acc[mt][nt][2 * half + 1] + b1 + x[i1];
            }
        }
    }
}

// ---------------- zero rowsum ------------------------------------------------
__global__ void zero_rowsum_kernel() {
    g_rowsum[blockIdx.x * 256 + threadIdx.x] = 0.f;
}

// ---------------- GroupNorm + coalesced transpose to [B, N, C] --------------
__global__ __launch_bounds__(512) void gn_kernel(
    const float* __restrict__ x, const float* __restrict__ gw,
    const float* __restrict__ gb)
{
    const int b = blockIdx.x >> 5;
    const int g = blockIdx.x & 31;
    const float* xp = x + ((size_t)(b * CH + g * CPG)) * NTOKB;

    float s = 0.f, ss = 0.f;
    const float4* xp4 = (const float4*)xp;
    for (int i = threadIdx.x; i < CPG * NTOKB / 4; i += 512) {
        float4 vv = xp4[i];
        s  += vv.x + vv.y + vv.z + vv.w;
        ss += vv.x * vv.x + vv.y * vv.y + vv.z * vv.z + vv.w * vv.w;
    }
    __shared__ float rs[16], rss[16], bc[2];
#pragma unroll
    for (int o = 16; o > 0; o >>= 1) {
        s  += __shfl_xor_sync(0xffffffffu, s, o);
        ss += __shfl_xor_sync(0xffffffffu, ss, o);
    }
    if ((threadIdx.x & 31) == 0) { rs[threadIdx.x >> 5] = s; rss[threadIdx.x >> 5] = ss; }
    __syncthreads();
    if (threadIdx.x < 32) {
        s  = (threadIdx.x < 16) ? rs[threadIdx.x]  : 0.f;
        ss = (threadIdx.x < 16) ? rss[threadIdx.x] : 0.f;
#pragma unroll
        for (int o = 8; o > 0; o >>= 1) {
            s  += __shfl_xor_sync(0xffffffffu, s, o);
            ss += __shfl_xor_sync(0xffffffffu, ss, o);
        }
        if (threadIdx.x == 0) {
            const float NEL = (float)(CPG * NTOKB);
            float mean = s / NEL;
            float var  = ss / NEL - mean * mean;
            bc[0] = mean;
            bc[1] = rsqrtf(var + EPS);
        }
    }
    __syncthreads();
    __shared__ float sa[CPG], sb2[CPG];
    if (threadIdx.x < CPG) {
        float a = bc[1] * gw[g * CPG + threadIdx.x];
        sa[threadIdx.x]  = a;
        sb2[threadIdx.x] = gb[g * CPG + threadIdx.x] - bc[0] * a;
    }
    __syncthreads();

    __shared__ float tile[CPG][132];
    const int c  = threadIdx.x >> 5, seg = threadIdx.x & 31;
    const int nl = threadIdx.x >> 2, cq  = threadIdx.x & 3;
    for (int t0 = 0; t0 < NTOKB; t0 += 128) {
        float4 vv = *(const float4*)(xp + (size_t)c * NTOKB + t0 + seg * 4);
        const float a = sa[c], bb = sb2[c];
        tile[c][seg * 4 + 0] = vv.x * a + bb;
        tile[c][seg * 4 + 1] = vv.y * a + bb;
        tile[c][seg * 4 + 2] = vv.z * a + bb;
        tile[c][seg * 4 + 3] = vv.w * a + bb;
        __syncthreads();
        float4 wv;
        wv.x = tile[cq * 4 + 0][nl];
        wv.y = tile[cq * 4 + 1][nl];
        wv.z = tile[cq * 4 + 2][nl];
        wv.w = tile[cq * 4 + 3][nl];
        *(float4*)(g_t + ((size_t)(b * NTOKB + t0 + nl)) * CH + g * CPG + cq * 4) = wv;
        __syncthreads();
    }
}

// ---------------- launch ----------------------------------------------------
extern "C" void kernel_launch(void* const* d_in, const int* in_sizes, int n_in,
                              void* d_out, int out_size)
{
    const float* x  = (const float*)d_in[0];
    const float* gw = (const float*)d_in[1];
    const float* gb = (const float*)d_in[2];
    const float* wq = (const float*)d_in[3];
    const float* bq = (const float*)d_in[4];
    const float* wk = (const float*)d_in[5];
    const float* bk = (const float*)d_in[6];
    const float* wv = (const float*)d_in[7];
    const float* bv = (const float*)d_in[8];
    const float* wo = (const float*)d_in[9];
    const float* bo = (const float*)d_in[10];
    float* out = (float*)d_out;

    float *t, *q, *k, *v, *o, *s;
    cudaGetSymbolAddress((void**)&t, g_t);
    cudaGetSymbolAddress((void**)&q, g_q);
    cudaGetSymbolAddress((void**)&k, g_k);
    cudaGetSymbolAddress((void**)&v, g_v);
    cudaGetSymbolAddress((void**)&o, g_o);
    cudaGetSymbolAddress((void**)&s, g_s);

    const int ntBytes = (int)sizeof(NTSm);   // 61,440
    const int nnBytes = (int)sizeof(NNSm);   // 56,832
    cudaFuncSetAttribute(gemm_qkv,   cudaFuncAttributeMaxDynamicSharedMemorySize, ntBytes);
    cudaFuncSetAttribute(gemm_s,     cudaFuncAttributeMaxDynamicSharedMemorySize, ntBytes);
    cudaFuncSetAttribute(gemm_av,    cudaFuncAttributeMaxDynamicSharedMemorySize, nnBytes);
    cudaFuncSetAttribute(gemm_out_k, cudaFuncAttributeMaxDynamicSharedMemorySize, ntBytes);

    // 0) zero softmax denominators (graph replays re-run this)
    zero_rowsum_kernel<<<NTOK / 256, 256>>>();

    // 1) GroupNorm -> token layout g_t [B*N, C]
    gn_kernel<<<BATCH * NGROUP, 512>>>(x, gw, gb);

    // 2) fused Q/K/V projections
    gemm_qkv<<<dim3(CH / 128, NTOK / 128, 3), 128, ntBytes>>>(t, wq, bq, q, wk, bk, k, wv, bv, v);

    // 3) S = exp(scale * Q K^T), row sums accumulated (no separate softmax)
    gemm_s<<<dim3(NTOKB / 128, NTOKB / 128, BATCH), 128, ntBytes>>>(q, k, s);

    // 4) O = (exp(S) V) / rowsum
    gemm_av<<<dim3(CH / 128, NTOKB / 128, BATCH), 128, nnBytes>>>(s, v, o);

    // 5) out = O wo^T + bo, transpose to [B,C,H,W], + residual
    gemm_out_k<<<dim3(CH / 128, NTOK / 128, 1), 128, ntBytes>>>(o, wo, bo, x, out);
}

// round 11
// speedup vs baseline: 4.2520x; 1.0906x over previous
#include <cuda_runtime.h>
#include <cuda_bf16.h>

#define BATCH  2
#define CH     512
#define NTOKB  4096              // tokens per batch (H*W)
#define NTOK   (BATCH * NTOKB)   // 8192
#define NGROUP 32
#define CPG    (CH / NGROUP)     // 16
#define EPS    1e-5f
#define SCALE  0.04419417382415922f   // 1/sqrt(512)

// ---------------- scratch (device globals; no allocations allowed) ----------
__device__ float g_t[(size_t)NTOK * CH];                 // normalized tokens [B*N, C]
__device__ float g_q[(size_t)NTOK * CH];
__device__ float g_k[(size_t)NTOK * CH];
__device__ float g_v[(size_t)NTOK * CH];
__device__ float g_o[(size_t)NTOK * CH];
__device__ __nv_bfloat16 g_sh[(size_t)BATCH * NTOKB * NTOKB];  // exp(scores), bf16, 64 MB
__device__ __nv_bfloat16 g_vt[(size_t)BATCH * CH * NTOKB];     // V^T bf16 [B][C][N]
__device__ float g_rowsum[NTOK];                          // softmax denominators

// ---------------- primitives ------------------------------------------------
__device__ __forceinline__ void mma_tf32(float* d, const unsigned* a, const unsigned* b) {
    asm volatile(
        "mma.sync.aligned.m16n8k8.row.col.f32.tf32.tf32.f32 "
        "{%0,%1,%2,%3}, {%4,%5,%6,%7}, {%8,%9}, {%0,%1,%2,%3};\n"
        : "+f"(d[0]), "+f"(d[1]), "+f"(d[2]), "+f"(d[3])
        : "r"(a[0]), "r"(a[1]), "r"(a[2]), "r"(a[3]), "r"(b[0]), "r"(b[1]));
}
__device__ __forceinline__ void mma_bf16(float* d, const unsigned* a, const unsigned* b) {
    asm volatile(
        "mma.sync.aligned.m16n8k16.row.col.f32.bf16.bf16.f32 "
        "{%0,%1,%2,%3}, {%4,%5,%6,%7}, {%8,%9}, {%0,%1,%2,%3};\n"
        : "+f"(d[0]), "+f"(d[1]), "+f"(d[2]), "+f"(d[3])
        : "r"(a[0]), "r"(a[1]), "r"(a[2]), "r"(a[3]), "r"(b[0]), "r"(b[1]));
}

__device__ __forceinline__ unsigned sptr(const void* p) {
    return (unsigned)__cvta_generic_to_shared(p);
}
#define CP16(dst, src) asm volatile("cp.async.cg.shared.global [%0], [%1], 16;" :: "r"(dst), "l"(src))
#define CPCOMMIT()     asm volatile("cp.async.commit_group;")
#define CPWAIT1()      asm volatile("cp.async.wait_group 1;")

#define PA  20    // fp32 pitch for [128 x 16] k-major tiles; conflict-free
#define PAH 24    // bf16 pitch for [128 x 16] bf16 tiles (12 b32); conflict-free

struct NTSm { float A[3][128][PA]; float B[3][128][PA]; };               // 61,440 B
struct AVSm { __nv_bfloat16 A[3][128][PAH]; __nv_bfloat16 B[3][128][PAH]; }; // 36,864 B

// [128 rows x 16 floats], rows stride ld (src pre-offset); 256 threads
__device__ __forceinline__ void load_t128x16(float (*dst)[PA], const float* src, int ld, int tid) {
#pragma unroll
    for (int i = 0; i < 2; i++) {
        int chunk = i * 256 + tid;
        int row = chunk >> 2, seg = chunk & 3;
        CP16(sptr(&dst[row][seg * 4]), src + (size_t)row * ld + seg * 4);
    }
}
// [128 rows x 16 bf16], rows stride ld; 256 threads (1 chunk each)
__device__ __forceinline__ void load_h128x16(__nv_bfloat16 (*dst)[PAH],
                                             const __nv_bfloat16* src, int ld, int tid) {
    int row = tid >> 1, seg = tid & 1;
    CP16(sptr(&dst[row][seg * 8]), src + (size_t)row * ld + seg * 8);
}

// ---------------- NT tf32 mainloop: C[128,128] += A[m0+.,k] * B[n0+.,k] -----
// 256 threads, 8 warps (2m x 4n), warp tile 64x32 = 4x4 m16n8k8 fragments.
__device__ __forceinline__ void nt_main(const float* A, const float* B, int K,
                                        NTSm* sm, float acc[4][4][4], int m0, int n0)
{
    const int tid = threadIdx.x;
    const int lane = tid & 31, w = tid >> 5;
    const int wm0 = (w >> 2) * 64, wn0 = (w & 3) * 32;
    const int fg = lane >> 2, fq = lane & 3;

    const float* Ab = A + (size_t)m0 * K;
    const float* Bb = B + (size_t)n0 * K;

    load_t128x16(sm->A[0], Ab, K, tid);
    load_t128x16(sm->B[0], Bb, K, tid);
    CPCOMMIT();
    load_t128x16(sm->A[1], Ab + 16, K, tid);
    load_t128x16(sm->B[1], Bb + 16, K, tid);
    CPCOMMIT();

    const int NK = K >> 4;
    int cur = 0, nxt = 2;
    for (int it = 0; it < NK; ++it) {
        CPWAIT1();
        __syncthreads();
        if (it + 2 < NK) {
            load_t128x16(sm->A[nxt], Ab + (it + 2) * 16, K, tid);
            load_t128x16(sm->B[nxt], Bb + (it + 2) * 16, K, tid);
        }
        CPCOMMIT();

        const unsigned (*As)[PA] = reinterpret_cast<const unsigned(*)[PA]>(sm->A[cur]);
        const unsigned (*Bs)[PA] = reinterpret_cast<const unsigned(*)[PA]>(sm->B[cur]);
#pragma unroll
        for (int ks = 0; ks < 16; ks += 8) {
            unsigned bf[4][2];
#pragma unroll
            for (int nt = 0; nt < 4; nt++) {
                bf[nt][0] = Bs[wn0 + nt * 8 + fg][ks + fq];
                bf[nt][1] = Bs[wn0 + nt * 8 + fg][ks + fq + 4];
            }
#pragma unroll
            for (int mt = 0; mt < 4; mt++) {
                unsigned af[4];
                const int am = wm0 + mt * 16 + fg;
                af[0] = As[am][ks + fq];     af[1] = As[am + 8][ks + fq];
                af[2] = As[am][ks + fq + 4]; af[3] = As[am + 8][ks + fq + 4];
#pragma unroll
                for (int nt = 0; nt < 4; nt++)
                    mma_tf32(acc[mt][nt], af, bf[nt]);
            }
        }
        cur = (cur == 2) ? 0 : cur + 1;
        nxt = (nxt == 2) ? 0 : nxt + 1;
    }
}

// ---------------- NT bf16 mainloop (P @ V^T): same shape, k16 per mma -------
__device__ __forceinline__ void av_main(const __nv_bfloat16* A, const __nv_bfloat16* B, int K,
                                        AVSm* sm, float acc[4][4][4], int m0, int n0)
{
    const int tid = threadIdx.x;
    const int lane = tid & 31, w = tid >> 5;
    const int wm0 = (w >> 2) * 64, wn0 = (w & 3) * 32;
    const int fg = lane >> 2, fq = lane & 3;

    const __nv_bfloat16* Ab = A + (size_t)m0 * K;
    const __nv_bfloat16* Bb = B + (size_t)n0 * K;

    load_h128x16(sm->A[0], Ab, K, tid);
    load_h128x16(sm->B[0], Bb, K, tid);
    CPCOMMIT();
    load_h128x16(sm->A[1], Ab + 16, K, tid);
    load_h128x16(sm->B[1], Bb + 16, K, tid);
    CPCOMMIT();

    const int NK = K >> 4;
    int cur = 0, nxt = 2;
    for (int it = 0; it < NK; ++it) {
        CPWAIT1();
        __syncthreads();
        if (it + 2 < NK) {
            load_h128x16(sm->A[nxt], Ab + (it + 2) * 16, K, tid);
            load_h128x16(sm->B[nxt], Bb + (it + 2) * 16, K, tid);
        }
        CPCOMMIT();

        const unsigned (*As)[PAH / 2] = reinterpret_cast<const unsigned(*)[PAH / 2]>(sm->A[cur]);
        const unsigned (*Bs)[PAH / 2] = reinterpret_cast<const unsigned(*)[PAH / 2]>(sm->B[cur]);
        unsigned bf[4][2];
#pragma unroll
        for (int nt = 0; nt < 4; nt++) {
            bf[nt][0] = Bs[wn0 + nt * 8 + fg][fq];
            bf[nt][1] = Bs[wn0 + nt * 8 + fg][fq + 4];
        }
#pragma unroll
        for (int mt = 0; mt < 4; mt++) {
            unsigned af[4];
            const int am = wm0 + mt * 16 + fg;
            af[0] = As[am][fq];     af[1] = As[am + 8][fq];
            af[2] = As[am][fq + 4]; af[3] = As[am + 8][fq + 4];
#pragma unroll
            for (int nt = 0; nt < 4; nt++)
                mma_bf16(acc[mt][nt], af, bf[nt]);
        }
        cur = (cur == 2) ? 0 : cur + 1;
        nxt = (nxt == 2) ? 0 : nxt + 1;
    }
}

// ---------------- standard epilogue -----------------------------------------
__device__ __forceinline__ void nt_epi(float acc[4][4][4], const float* bias,
                                       float* Cc, int ldc, int m0, int n0)
{
    const int tid = threadIdx.x, lane = tid & 31, w = tid >> 5;
    const int wm0 = (w >> 2) * 64, wn0 = (w & 3) * 32;
    const int fg = lane >> 2, fq = lane & 3;
#pragma unroll
    for (int nt = 0; nt < 4; nt++) {
        const int col = n0 + wn0 + nt * 8 + 2 * fq;
        const float b0 = bias ? bias[col]     : 0.f;
        const float b1 = bias ? bias[col + 1] : 0.f;
#pragma unroll
        for (int mt = 0; mt < 4; mt++) {
            const int row = m0 + wm0 + mt * 16 + fg;
            float2 v0 = { acc[mt][nt][0] + b0, acc[mt][nt][1] + b1 };
            float2 v1 = { acc[mt][nt][2] + b0, acc[mt][nt][3] + b1 };
            *(float2*)&Cc[(size_t)row * ldc + col]       = v0;
            *(float2*)&Cc[(size_t)(row + 8) * ldc + col] = v1;
        }
    }
}

// ---------------- kernels ---------------------------------------------------
__global__ __launch_bounds__(256, 2) void gemm_qkv(
    const float* __restrict__ t,
    const float* __restrict__ wq, const float* __restrict__ bq, float* __restrict__ q,
    const float* __restrict__ wk, const float* __restrict__ bk, float* __restrict__ k,
    const float* __restrict__ wv, const float* __restrict__ bv, float* __restrict__ v)
{
    extern __shared__ char dynsm[];
    NTSm* sm = (NTSm*)dynsm;
    const float* W  = blockIdx.z == 0 ? wq : blockIdx.z == 1 ? wk : wv;
    const float* bs = blockIdx.z == 0 ? bq : blockIdx.z == 1 ? bk : bv;
    float*       C  = blockIdx.z == 0 ? q  : blockIdx.z == 1 ? k  : v;
    float acc[4][4][4] = {};
    nt_main(t, W, CH, sm, acc, blockIdx.y * 128, blockIdx.x * 128);
    nt_epi(acc, bs, C, CH, blockIdx.y * 128, blockIdx.x * 128);
}

// S-gemm: writes exp(scale * q.k) in bf16 and accumulates fp32 row sums.
__global__ __launch_bounds__(256, 2) void gemm_s(
    const float* __restrict__ q, const float* __restrict__ k)
{
    extern __shared__ char dynsm[];
    NTSm* sm = (NTSm*)dynsm;
    const size_t zo = (size_t)blockIdx.z * NTOKB * CH;
    const int m0 = blockIdx.y * 128, n0 = blockIdx.x * 128;
    float acc[4][4][4] = {};
    nt_main(q + zo, k + zo, CH, sm, acc, m0, n0);

    __nv_bfloat16* S = g_sh + (size_t)blockIdx.z * NTOKB * NTOKB;
    const int tid = threadIdx.x, lane = tid & 31, w = tid >> 5;
    const int wm0 = (w >> 2) * 64, wn0 = (w & 3) * 32;
    const int fg = lane >> 2, fq = lane & 3;

    float rsum[4][2] = {};
#pragma unroll
    for (int nt = 0; nt < 4; nt++) {
        const int col = n0 + wn0 + nt * 8 + 2 * fq;
#pragma unroll
        for (int mt = 0; mt < 4; mt++) {
            const int row = m0 + wm0 + mt * 16 + fg;
            float e0 = __expf(SCALE * acc[mt][nt][0]);
            float e1 = __expf(SCALE * acc[mt][nt][1]);
            float e2 = __expf(SCALE * acc[mt][nt][2]);
            float e3 = __expf(SCALE * acc[mt][nt][3]);
            *(__nv_bfloat162*)&S[(size_t)row * NTOKB + col]       = __floats2bfloat162_rn(e0, e1);
            *(__nv_bfloat162*)&S[(size_t)(row + 8) * NTOKB + col] = __floats2bfloat162_rn(e2, e3);
            rsum[mt][0] += e0 + e1;
            rsum[mt][1] += e2 + e3;
        }
    }
    const int rbase = blockIdx.z * NTOKB + m0 + wm0;
#pragma unroll
    for (int mt = 0; mt < 4; mt++) {
#pragma unroll
        for (int half = 0; half < 2; half++) {
            float vv = rsum[mt][half];
            vv += __shfl_xor_sync(0xffffffffu, vv, 1);
            vv += __shfl_xor_sync(0xffffffffu, vv, 2);
            if (fq == 0)
                atomicAdd(&g_rowsum[rbase + mt * 16 + fg + 8 * half], vv);
        }
    }
}

// V transpose + convert:  g_v [B*N, C] fp32  ->  g_vt [B, C, N] bf16
__global__ __launch_bounds__(256) void tv_kernel(const float* __restrict__ v)
{
    __shared__ float tile[32][33];
    const int b  = blockIdx.z;
    const int tx = threadIdx.x & 31, ty = threadIdx.x >> 5;   // 32 x 8
    const int ch0 = blockIdx.x * 32, tk0 = blockIdx.y * 32;
#pragma unroll
    for (int i = 0; i < 32; i += 8)
        tile[ty + i][tx] = v[((size_t)(b * NTOKB + tk0 + ty + i)) * CH + ch0 + tx];
    __syncthreads();
#pragma unroll
    for (int i = 0; i < 32; i += 8)
        g_vt[((size_t)(b * CH + ch0 + ty + i)) * NTOKB + tk0 + tx] =
            __float2bfloat16(tile[tx][ty + i]);
}

// AV-gemm (bf16 NT): O[q, ch] = (P @ V) / rowsum
__global__ __launch_bounds__(256, 2) void gemm_av(float* __restrict__ o)
{
    extern __shared__ char dynsm[];
    AVSm* sm = (AVSm*)dynsm;
    const int m0 = blockIdx.y * 128, n0 = blockIdx.x * 128;
    float acc[4][4][4] = {};
    av_main(g_sh + (size_t)blockIdx.z * NTOKB * NTOKB,
            g_vt + (size_t)blockIdx.z * CH * NTOKB,
            NTOKB, sm, acc, m0, n0);

    float* O = o + (size_t)blockIdx.z * NTOKB * CH;
    const int tid = threadIdx.x, lane = tid & 31, w = tid >> 5;
    const int wm0 = (w >> 2) * 64, wn0 = (w & 3) * 32;
    const int fg = lane >> 2, fq = lane & 3;

    const int rbase = blockIdx.z * NTOKB + m0 + wm0;
    float inv[4][2];
#pragma unroll
    for (int mt = 0; mt < 4; mt++) {
        inv[mt][0] = 1.f / g_rowsum[rbase + mt * 16 + fg];
        inv[mt][1] = 1.f / g_rowsum[rbase + mt * 16 + fg + 8];
    }
#pragma unroll
    for (int nt = 0; nt < 4; nt++) {
        const int col = n0 + wn0 + nt * 8 + 2 * fq;
#pragma unroll
        for (int mt = 0; mt < 4; mt++) {
            const int row = m0 + wm0 + mt * 16 + fg;
            float2 v0 = { acc[mt][nt][0] * inv[mt][0], acc[mt][nt][1] * inv[mt][0] };
            float2 v1 = { acc[mt][nt][2] * inv[mt][1], acc[mt][nt][3] * inv[mt][1] };
            *(float2*)&O[(size_t)row * CH + col]       = v0;
            *(float2*)&O[(size_t)(row + 8) * CH + col] = v1;
        }
    }
}

__global__ __launch_bounds__(256, 2) void gemm_out_k(
    const float* __restrict__ o, const float* __restrict__ wo,
    const float* __restrict__ bo, const float* __restrict__ x, float* __restrict__ out)
{
    extern __shared__ char dynsm[];
    NTSm* sm = (NTSm*)dynsm;
    const int m0 = blockIdx.y * 128, n0 = blockIdx.x * 128;
    float acc[4][4][4] = {};
    nt_main(o, wo, CH, sm, acc, m0, n0);

    const int tid = threadIdx.x, lane = tid & 31, w = tid >> 5;
    const int wm0 = (w >> 2) * 64, wn0 = (w & 3) * 32;
    const int fg = lane >> 2, fq = lane & 3;
#pragma unroll
    for (int nt = 0; nt < 4; nt++) {
        const int col = n0 + wn0 + nt * 8 + 2 * fq;
        const float b0 = bo[col];
        const float b1 = bo[col + 1];
#pragma unroll
        for (int mt = 0; mt < 4; mt++) {
#pragma unroll
            for (int half = 0; half < 2; half++) {
                const int row = m0 + wm0 + mt * 16 + fg + 8 * half;  // global token
                const int b = row >> 12;
                const int n = row & (NTOKB - 1);
                const size_t i0 = ((size_t)(b * CH + col)) * NTOKB + n;
                const size_t i1 = i0 + NTOKB;
                out[i0] = acc[mt][nt][2 * half + 0] + b0 + x[i0];
                out[i1] = acc[mt][nt][2 * half + 1] + b1 + x[i1];
            }
        }
    }
}

// ---------------- zero rowsum ------------------------------------------------
__global__ void zero_rowsum_kernel() {
    g_rowsum[blockIdx.x * 256 + threadIdx.x] = 0.f;
}

// ---------------- GroupNorm + coalesced transpose to [B, N, C] --------------
__global__ __launch_bounds__(512) void gn_kernel(
    const float* __restrict__ x, const float* __restrict__ gw,
    const float* __restrict__ gb)
{
    const int b = blockIdx.x >> 5;
    const int g = blockIdx.x & 31;
    const float* xp = x + ((size_t)(b * CH + g * CPG)) * NTOKB;

    float s = 0.f, ss = 0.f;
    const float4* xp4 = (const float4*)xp;
    for (int i = threadIdx.x; i < CPG * NTOKB / 4; i += 512) {
        float4 vv = xp4[i];
        s  += vv.x + vv.y + vv.z + vv.w;
        ss += vv.x * vv.x + vv.y * vv.y + vv.z * vv.z + vv.w * vv.w;
    }
    __shared__ float rs[16], rss[16], bc[2];
#pragma unroll
    for (int o = 16; o > 0; o >>= 1) {
        s  += __shfl_xor_sync(0xffffffffu, s, o);
        ss += __shfl_xor_sync(0xffffffffu, ss, o);
    }
    if ((threadIdx.x & 31) == 0) { rs[threadIdx.x >> 5] = s; rss[threadIdx.x >> 5] = ss; }
    __syncthreads();
    if (threadIdx.x < 32) {
        s  = (threadIdx.x < 16) ? rs[threadIdx.x]  : 0.f;
        ss = (threadIdx.x < 16) ? rss[threadIdx.x] : 0.f;
#pragma unroll
        for (int o = 8; o > 0; o >>= 1) {
            s  += __shfl_xor_sync(0xffffffffu, s, o);
            ss += __shfl_xor_sync(0xffffffffu, ss, o);
        }
        if (threadIdx.x == 0) {
            const float NEL = (float)(CPG * NTOKB);
            float mean = s / NEL;
            float var  = ss / NEL - mean * mean;
            bc[0] = mean;
            bc[1] = rsqrtf(var + EPS);
        }
    }
    __syncthreads();
    __shared__ float sa[CPG], sb2[CPG];
    if (threadIdx.x < CPG) {
        float a = bc[1] * gw[g * CPG + threadIdx.x];
        sa[threadIdx.x]  = a;
        sb2[threadIdx.x] = gb[g * CPG + threadIdx.x] - bc[0] * a;
    }
    __syncthreads();

    __shared__ float tile[CPG][132];
    const int c  = threadIdx.x >> 5, seg = threadIdx.x & 31;
    const int nl = threadIdx.x >> 2, cq  = threadIdx.x & 3;
    for (int t0 = 0; t0 < NTOKB; t0 += 128) {
        float4 vv = *(const float4*)(xp + (size_t)c * NTOKB + t0 + seg * 4);
        const float a = sa[c], bb = sb2[c];
        tile[c][seg * 4 + 0] = vv.x * a + bb;
        tile[c][seg * 4 + 1] = vv.y * a + bb;
        tile[c][seg * 4 + 2] = vv.z * a + bb;
        tile[c][seg * 4 + 3] = vv.w * a + bb;
        __syncthreads();
        float4 wv;
        wv.x = tile[cq * 4 + 0][nl];
        wv.y = tile[cq * 4 + 1][nl];
        wv.z = tile[cq * 4 + 2][nl];
        wv.w = tile[cq * 4 + 3][nl];
        *(float4*)(g_t + ((size_t)(b * NTOKB + t0 + nl)) * CH + g * CPG + cq * 4) = wv;
        __syncthreads();
    }
}

// ---------------- launch ----------------------------------------------------
extern "C" void kernel_launch(void* const* d_in, const int* in_sizes, int n_in,
                              void* d_out, int out_size)
{
    const float* x  = (const float*)d_in[0];
    const float* gw = (const float*)d_in[1];
    const float* gb = (const float*)d_in[2];
    const float* wq = (const float*)d_in[3];
    const float* bq = (const float*)d_in[4];
    const float* wk = (const float*)d_in[5];
    const float* bk = (const float*)d_in[6];
    const float* wv = (const float*)d_in[7];
    const float* bv = (const float*)d_in[8];
    const float* wo = (const float*)d_in[9];
    const float* bo = (const float*)d_in[10];
    float* out = (float*)d_out;

    float *t, *q, *k, *v, *o;
    cudaGetSymbolAddress((void**)&t, g_t);
    cudaGetSymbolAddress((void**)&q, g_q);
    cudaGetSymbolAddress((void**)&k, g_k);
    cudaGetSymbolAddress((void**)&v, g_v);
    cudaGetSymbolAddress((void**)&o, g_o);

    const int ntBytes = (int)sizeof(NTSm);   // 61,440
    const int avBytes = (int)sizeof(AVSm);   // 36,864
    cudaFuncSetAttribute(gemm_qkv,   cudaFuncAttributeMaxDynamicSharedMemorySize, ntBytes);
    cudaFuncSetAttribute(gemm_s,     cudaFuncAttributeMaxDynamicSharedMemorySize, ntBytes);
    cudaFuncSetAttribute(gemm_av,    cudaFuncAttributeMaxDynamicSharedMemorySize, avBytes);
    cudaFuncSetAttribute(gemm_out_k, cudaFuncAttributeMaxDynamicSharedMemorySize, ntBytes);

    // 0) zero softmax denominators (graph replays re-run this)
    zero_rowsum_kernel<<<NTOK / 256, 256>>>();

    // 1) GroupNorm -> token layout g_t [B*N, C]
    gn_kernel<<<BATCH * NGROUP, 512>>>(x, gw, gb);

    // 2) fused Q/K/V projections
    gemm_qkv<<<dim3(CH / 128, NTOK / 128, 3), 256, ntBytes>>>(t, wq, bq, q, wk, bk, k, wv, bv, v);

    // 2b) V -> V^T bf16
    tv_kernel<<<dim3(CH / 32, NTOKB / 32, BATCH), 256>>>(v);

    // 3) S = exp(scale * Q K^T) -> bf16, row sums accumulated
    gemm_s<<<dim3(NTOKB / 128, NTOKB / 128, BATCH), 256, ntBytes>>>(q, k);

    // 4) O = (P V) / rowsum   (bf16 NT gemm)
    gemm_av<<<dim3(CH / 128, NTOKB / 128, BATCH), 256, avBytes>>>(o);

    // 5) out = O wo^T + bo, transpose to [B,C,H,W], + residual
    gemm_out_k<<<dim3(CH / 128, NTOK / 128, 1), 256, ntBytes>>>(o, wo, bo, x, out);
}

// round 13
// speedup vs baseline: 4.4197x; 1.0394x over previous
#include <cuda_runtime.h>
#include <cuda_bf16.h>
#include <cstdint>

#define BATCH  2
#define CH     512
#define NTOKB  4096              // tokens per batch (H*W)
#define NTOK   (BATCH * NTOKB)   // 8192
#define NGROUP 32
#define CPG    (CH / NGROUP)     // 16
#define EPS    1e-5f
#define SCALE  0.04419417382415922f   // 1/sqrt(512)

// ---------------- scratch (device globals; no allocations allowed) ----------
__device__ float g_t[(size_t)NTOK * CH];                 // normalized tokens [B*N, C]
__device__ float g_q[(size_t)NTOK * CH];
__device__ float g_k[(size_t)NTOK * CH];
__device__ float g_v[(size_t)NTOK * CH];
__device__ float g_o[(size_t)NTOK * CH];
__device__ __nv_bfloat16 g_sh[(size_t)BATCH * NTOKB * NTOKB];  // exp(scores), bf16, 64 MB
__device__ __nv_bfloat16 g_vt[(size_t)BATCH * CH * NTOKB];     // V^T bf16 [B][C][N]
__device__ float g_rowsum[NTOK];                          // softmax denominators

// ---------------- primitives ------------------------------------------------
__device__ __forceinline__ void mma_tf32(float* d, const unsigned* a, const unsigned* b) {
    asm volatile(
        "mma.sync.aligned.m16n8k8.row.col.f32.tf32.tf32.f32 "
        "{%0,%1,%2,%3}, {%4,%5,%6,%7}, {%8,%9}, {%0,%1,%2,%3};\n"
        : "+f"(d[0]), "+f"(d[1]), "+f"(d[2]), "+f"(d[3])
        : "r"(a[0]), "r"(a[1]), "r"(a[2]), "r"(a[3]), "r"(b[0]), "r"(b[1]));
}
__device__ __forceinline__ void mma_bf16(float* d, const unsigned* a, const unsigned* b) {
    asm volatile(
        "mma.sync.aligned.m16n8k16.row.col.f32.bf16.bf16.f32 "
        "{%0,%1,%2,%3}, {%4,%5,%6,%7}, {%8,%9}, {%0,%1,%2,%3};\n"
        : "+f"(d[0]), "+f"(d[1]), "+f"(d[2]), "+f"(d[3])
        : "r"(a[0]), "r"(a[1]), "r"(a[2]), "r"(a[3]), "r"(b[0]), "r"(b[1]));
}

__device__ __forceinline__ unsigned smem_u32(const void* p) {
    return (unsigned)__cvta_generic_to_shared(p);
}
#define CP16(dst, src) asm volatile("cp.async.cg.shared.global [%0], [%1], 16;" :: "r"(dst), "l"(src))
#define CPCOMMIT()     asm volatile("cp.async.commit_group;")
#define CPWAIT1()      asm volatile("cp.async.wait_group 1;")

// ============================================================================
// Big-tile mainloop (S and AV): block 128x256, 256 thr = 8 warps (2m x 4n),
// warp tile 64x64 -> 4x8 fragments.  k-chunk = 64 bytes per row
// (16 fp32 for tf32 / 32 bf16 for bf16) -> 2 mma k-steps per chunk.
// Same smem addressing for both dtypes: pitch 20 b32, conflict-free.
// ============================================================================
#define P2 20
struct SM2 { unsigned A[3][128][P2]; unsigned B[3][256][P2]; };   // 92,160 B

__device__ __forceinline__ void load2_A(unsigned (*dst)[P2], const char* src,
                                        size_t ld, int tid) {
#pragma unroll
    for (int i = 0; i < 2; i++) {
        int c = i * 256 + tid;
        int r = c >> 2, s = c & 3;
        CP16(smem_u32(&dst[r][s * 4]), src + (size_t)r * ld + s * 16);
    }
}
__device__ __forceinline__ void load2_B(unsigned (*dst)[P2], const char* src,
                                        size_t ld, int tid) {
#pragma unroll
    for (int i = 0; i < 4; i++) {
        int c = i * 256 + tid;
        int r = c >> 2, s = c & 3;
        CP16(smem_u32(&dst[r][s * 4]), src + (size_t)r * ld + s * 16);
    }
}

template<bool BF16>
__device__ __forceinline__ void main2(const char* Ag, const char* Bg,
                                      size_t lda, size_t ldb, int NK,
                                      SM2* sm, float acc[4][8][4])
{
    const int tid = threadIdx.x;
    const int lane = tid & 31, w = tid >> 5;
    const int wm0 = (w >> 2) * 64, wn0 = (w & 3) * 64;
    const int fg = lane >> 2, fq = lane & 3;

    load2_A(sm->A[0], Ag, lda, tid);
    load2_B(sm->B[0], Bg, ldb, tid);
    CPCOMMIT();
    load2_A(sm->A[1], Ag + 64, lda, tid);
    load2_B(sm->B[1], Bg + 64, ldb, tid);
    CPCOMMIT();

    int cur = 0, nxt = 2;
    for (int it = 0; it < NK; ++it) {
        CPWAIT1();
        __syncthreads();
        if (it + 2 < NK) {
            load2_A(sm->A[nxt], Ag + (size_t)(it + 2) * 64, lda, tid);
            load2_B(sm->B[nxt], Bg + (size_t)(it + 2) * 64, ldb, tid);
        }
        CPCOMMIT();

        const unsigned (*As)[P2] = sm->A[cur];
        const unsigned (*Bs)[P2] = sm->B[cur];
#pragma unroll
        for (int ks = 0; ks < 2; ks++) {
            const int c0 = ks * 8 + fq;           // b32 column of first frag reg
            unsigned bf[8][2];
#pragma unroll
            for (int nt = 0; nt < 8; nt++) {
                const int bn = wn0 + nt * 8 + fg;
                bf[nt][0] = Bs[bn][c0];
                bf[nt][1] = Bs[bn][c0 + 4];
            }
#pragma unroll
            for (int mt = 0; mt < 4; mt++) {
                unsigned af[4];
                const int am = wm0 + mt * 16 + fg;
                af[0] = As[am][c0];     af[1] = As[am + 8][c0];
                af[2] = As[am][c0 + 4]; af[3] = As[am + 8][c0 + 4];
#pragma unroll
                for (int nt = 0; nt < 8; nt++) {
                    if (BF16) mma_bf16(acc[mt][nt], af, bf[nt]);
                    else      mma_tf32(acc[mt][nt], af, bf[nt]);
                }
            }
        }
        cur = (cur == 2) ? 0 : cur + 1;
        nxt = (nxt == 2) ? 0 : nxt + 1;
    }
}

// S-gemm: S = exp(scale * Q K^T) -> bf16 P + fp32 rowsum (no-max softmax)
__global__ __launch_bounds__(256) void gemm_s(
    const float* __restrict__ q, const float* __restrict__ k)
{
    extern __shared__ char dynsm[];
    SM2* sm = (SM2*)dynsm;
    const int m0 = blockIdx.y * 128, n0 = blockIdx.x * 256, z = blockIdx.z;
    const char* Ag = (const char*)(q + (size_t)(z * NTOKB + m0) * CH);
    const char* Bg = (const char*)(k + (size_t)(z * NTOKB + n0) * CH);
    float acc[4][8][4] = {};
    main2<false>(Ag, Bg, (size_t)CH * 4, (size_t)CH * 4, (CH * 4) / 64, sm, acc);

    __nv_bfloat16* S = g_sh + (size_t)z * NTOKB * NTOKB;
    const int tid = threadIdx.x, lane = tid & 31, w = tid >> 5;
    const int wm0 = (w >> 2) * 64, wn0 = (w & 3) * 64;
    const int fg = lane >> 2, fq = lane & 3;

    float rsum[4][2] = {};
#pragma unroll
    for (int nt = 0; nt < 8; nt++) {
        const int col = n0 + wn0 + nt * 8 + 2 * fq;
#pragma unroll
        for (int mt = 0; mt < 4; mt++) {
            const int row = m0 + wm0 + mt * 16 + fg;
            float e0 = __expf(SCALE * acc[mt][nt][0]);
            float e1 = __expf(SCALE * acc[mt][nt][1]);
            float e2 = __expf(SCALE * acc[mt][nt][2]);
            float e3 = __expf(SCALE * acc[mt][nt][3]);
            *(__nv_bfloat162*)&S[(size_t)row * NTOKB + col]       = __floats2bfloat162_rn(e0, e1);
            *(__nv_bfloat162*)&S[(size_t)(row + 8) * NTOKB + col] = __floats2bfloat162_rn(e2, e3);
            rsum[mt][0] += e0 + e1;
            rsum[mt][1] += e2 + e3;
        }
    }
    const int rbase = z * NTOKB + m0 + wm0;
#pragma unroll
    for (int mt = 0; mt < 4; mt++) {
#pragma unroll
        for (int half = 0; half < 2; half++) {
            float vv = rsum[mt][half];
            vv += __shfl_xor_sync(0xffffffffu, vv, 1);
            vv += __shfl_xor_sync(0xffffffffu, vv, 2);
            if (fq == 0)
                atomicAdd(&g_rowsum[rbase + mt * 16 + fg + 8 * half], vv);
        }
    }
}

// AV-gemm (bf16): O[q, ch] = (P @ V) / rowsum.  A=P rows=query, B=V^T rows=ch.
__global__ __launch_bounds__(256) void gemm_av(float* __restrict__ o)
{
    extern __shared__ char dynsm[];
    SM2* sm = (SM2*)dynsm;
    const int m0 = blockIdx.y * 128, n0 = blockIdx.x * 256, z = blockIdx.z;
    const char* Ag = (const char*)(g_sh + (size_t)z * NTOKB * NTOKB + (size_t)m0 * NTOKB);
    const char* Bg = (const char*)(g_vt + (size_t)z * CH * NTOKB + (size_t)n0 * NTOKB);
    float acc[4][8][4] = {};
    main2<true>(Ag, Bg, (size_t)NTOKB * 2, (size_t)NTOKB * 2, (NTOKB * 2) / 64, sm, acc);

    float* O = o + (size_t)z * NTOKB * CH;
    const int tid = threadIdx.x, lane = tid & 31, w = tid >> 5;
    const int wm0 = (w >> 2) * 64, wn0 = (w & 3) * 64;
    const int fg = lane >> 2, fq = lane & 3;

    const int rbase = z * NTOKB + m0 + wm0;
    float inv[4][2];
#pragma unroll
    for (int mt = 0; mt < 4; mt++) {
        inv[mt][0] = 1.f / g_rowsum[rbase + mt * 16 + fg];
        inv[mt][1] = 1.f / g_rowsum[rbase + mt * 16 + fg + 8];
    }
#pragma unroll
    for (int nt = 0; nt < 8; nt++) {
        const int col = n0 + wn0 + nt * 8 + 2 * fq;
#pragma unroll
        for (int mt = 0; mt < 4; mt++) {
            const int row = m0 + wm0 + mt * 16 + fg;
            float2 v0 = { acc[mt][nt][0] * inv[mt][0], acc[mt][nt][1] * inv[mt][0] };
            float2 v1 = { acc[mt][nt][2] * inv[mt][1], acc[mt][nt][3] * inv[mt][1] };
            *(float2*)&O[(size_t)row * CH + col]       = v0;
            *(float2*)&O[(size_t)(row + 8) * CH + col] = v1;
        }
    }
}

// ============================================================================
// 128x128 tf32 path (QKV projections + out-proj) — proven R11 config.
// ============================================================================
#define PA 20
struct NTSm { float A[3][128][PA]; float B[3][128][PA]; };   // 61,440 B

__device__ __forceinline__ void load_t128x16(float (*dst)[PA], const float* src, int ld, int tid) {
#pragma unroll
    for (int i = 0; i < 2; i++) {
        int chunk = i * 256 + tid;
        int row = chunk >> 2, seg = chunk & 3;
        CP16(smem_u32(&dst[row][seg * 4]), src + (size_t)row * ld + seg * 4);
    }
}

__device__ __forceinline__ void nt_main(const float* A, const float* B, int K,
                                        NTSm* sm, float acc[4][4][4], int m0, int n0)
{
    const int tid = threadIdx.x;
    const int lane = tid & 31, w = tid >> 5;
    const int wm0 = (w >> 2) * 64, wn0 = (w & 3) * 32;
    const int fg = lane >> 2, fq = lane & 3;

    const float* Ab = A + (size_t)m0 * K;
    const float* Bb = B + (size_t)n0 * K;

    load_t128x16(sm->A[0], Ab, K, tid);
    load_t128x16(sm->B[0], Bb, K, tid);
    CPCOMMIT();
    load_t128x16(sm->A[1], Ab + 16, K, tid);
    load_t128x16(sm->B[1], Bb + 16, K, tid);
    CPCOMMIT();

    const int NK = K >> 4;
    int cur = 0, nxt = 2;
    for (int it = 0; it < NK; ++it) {
        CPWAIT1();
        __syncthreads();
        if (it + 2 < NK) {
            load_t128x16(sm->A[nxt], Ab + (it + 2) * 16, K, tid);
            load_t128x16(sm->B[nxt], Bb + (it + 2) * 16, K, tid);
        }
        CPCOMMIT();

        const unsigned (*As)[PA] = reinterpret_cast<const unsigned(*)[PA]>(sm->A[cur]);
        const unsigned (*Bs)[PA] = reinterpret_cast<const unsigned(*)[PA]>(sm->B[cur]);
#pragma unroll
        for (int ks = 0; ks < 16; ks += 8) {
            unsigned bf[4][2];
#pragma unroll
            for (int nt = 0; nt < 4; nt++) {
                bf[nt][0] = Bs[wn0 + nt * 8 + fg][ks + fq];
                bf[nt][1] = Bs[wn0 + nt * 8 + fg][ks + fq + 4];
            }
#pragma unroll
            for (int mt = 0; mt < 4; mt++) {
                unsigned af[4];
                const int am = wm0 + mt * 16 + fg;
                af[0] = As[am][ks + fq];     af[1] = As[am + 8][ks + fq];
                af[2] = As[am][ks + fq + 4]; af[3] = As[am + 8][ks + fq + 4];
#pragma unroll
                for (int nt = 0; nt < 4; nt++)
                    mma_tf32(acc[mt][nt], af, bf[nt]);
            }
        }
        cur = (cur == 2) ? 0 : cur + 1;
        nxt = (nxt == 2) ? 0 : nxt + 1;
    }
}

__device__ __forceinline__ void nt_epi(float acc[4][4][4], const float* bias,
                                       float* Cc, int ldc, int m0, int n0)
{
    const int tid = threadIdx.x, lane = tid & 31, w = tid >> 5;
    const int wm0 = (w >> 2) * 64, wn0 = (w & 3) * 32;
    const int fg = lane >> 2, fq = lane & 3;
#pragma unroll
    for (int nt = 0; nt < 4; nt++) {
        const int col = n0 + wn0 + nt * 8 + 2 * fq;
        const float b0 = bias ? bias[col]     : 0.f;
        const float b1 = bias ? bias[col + 1] : 0.f;
#pragma unroll
        for (int mt = 0; mt < 4; mt++) {
            const int row = m0 + wm0 + mt * 16 + fg;
            float2 v0 = { acc[mt][nt][0] + b0, acc[mt][nt][1] + b1 };
            float2 v1 = { acc[mt][nt][2] + b0, acc[mt][nt][3] + b1 };
            *(float2*)&Cc[(size_t)row * ldc + col]       = v0;
            *(float2*)&Cc[(size_t)(row + 8) * ldc + col] = v1;
        }
    }
}

__global__ __launch_bounds__(256, 2) void gemm_qkv(
    const float* __restrict__ t,
    const float* __restrict__ wq, const float* __restrict__ bq, float* __restrict__ q,
    const float* __restrict__ wk, const float* __restrict__ bk, float* __restrict__ k,
    const float* __restrict__ wv, const float* __restrict__ bv, float* __restrict__ v)
{
    extern __shared__ char dynsm[];
    NTSm* sm = (NTSm*)dynsm;
    const float* W  = blockIdx.z == 0 ? wq : blockIdx.z == 1 ? wk : wv;
    const float* bs = blockIdx.z == 0 ? bq : blockIdx.z == 1 ? bk : bv;
    float*       C  = blockIdx.z == 0 ? q  : blockIdx.z == 1 ? k  : v;
    float acc[4][4][4] = {};
    nt_main(t, W, CH, sm, acc, blockIdx.y * 128, blockIdx.x * 128);
    nt_epi(acc, bs, C, CH, blockIdx.y * 128, blockIdx.x * 128);
}

__global__ __launch_bounds__(256, 2) void gemm_out_k(
    const float* __restrict__ o, const float* __restrict__ wo,
    const float* __restrict__ bo, const float* __restrict__ x, float* __restrict__ out)
{
    extern __shared__ char dynsm[];
    NTSm* sm = (NTSm*)dynsm;
    const int m0 = blockIdx.y * 128, n0 = blockIdx.x * 128;
    float acc[4][4][4] = {};
    nt_main(o, wo, CH, sm, acc, m0, n0);

    const int tid = threadIdx.x, lane = tid & 31, w = tid >> 5;
    const int wm0 = (w >> 2) * 64, wn0 = (w & 3) * 32;
    const int fg = lane >> 2, fq = lane & 3;
#pragma unroll
    for (int nt = 0; nt < 4; nt++) {
        const int col = n0 + wn0 + nt * 8 + 2 * fq;
        const float b0 = bo[col];
        const float b1 = bo[col + 1];
#pragma unroll
        for (int mt = 0; mt < 4; mt++) {
#pragma unroll
            for (int half = 0; half < 2; half++) {
                const int row = m0 + wm0 + mt * 16 + fg + 8 * half;  // global token
                const int b = row >> 12;
                const int n = row & (NTOKB - 1);
                const size_t i0 = ((size_t)(b * CH + col)) * NTOKB + n;
                const size_t i1 = i0 + NTOKB;
                out[i0] = acc[mt][nt][2 * half + 0] + b0 + x[i0];
                out[i1] = acc[mt][nt][2 * half + 1] + b1 + x[i1];
            }
        }
    }
}

// ---------------- V transpose + convert to bf16 [B][C][N] -------------------
__global__ __launch_bounds__(256) void tv_kernel(const float* __restrict__ v)
{
    __shared__ float tile[32][33];
    const int b  = blockIdx.z;
    const int tx = threadIdx.x & 31, ty = threadIdx.x >> 5;   // 32 x 8
    const int ch0 = blockIdx.x * 32, tk0 = blockIdx.y * 32;
#pragma unroll
    for (int i = 0; i < 32; i += 8)
        tile[ty + i][tx] = v[((size_t)(b * NTOKB + tk0 + ty + i)) * CH + ch0 + tx];
    __syncthreads();
#pragma unroll
    for (int i = 0; i < 32; i += 8)
        g_vt[((size_t)(b * CH + ch0 + ty + i)) * NTOKB + tk0 + tx] =
            __float2bfloat16(tile[tx][ty + i]);
}

// ---------------- zero rowsum ------------------------------------------------
__global__ void zero_rowsum_kernel() {
    g_rowsum[blockIdx.x * 256 + threadIdx.x] = 0.f;
}

// ---------------- GroupNorm + coalesced transpose to [B, N, C] --------------
__global__ __launch_bounds__(512) void gn_kernel(
    const float* __restrict__ x, const float* __restrict__ gw,
    const float* __restrict__ gb)
{
    const int b = blockIdx.x >> 5;
    const int g = blockIdx.x & 31;
    const float* xp = x + ((size_t)(b * CH + g * CPG)) * NTOKB;

    float s = 0.f, ss = 0.f;
    const float4* xp4 = (const float4*)xp;
    for (int i = threadIdx.x; i < CPG * NTOKB / 4; i += 512) {
        float4 vv = xp4[i];
        s  += vv.x + vv.y + vv.z + vv.w;
        ss += vv.x * vv.x + vv.y * vv.y + vv.z * vv.z + vv.w * vv.w;
    }
    __shared__ float rs[16], rss[16], bc[2];
#pragma unroll
    for (int o = 16; o > 0; o >>= 1) {
        s  += __shfl_xor_sync(0xffffffffu, s, o);
        ss += __shfl_xor_sync(0xffffffffu, ss, o);
    }
    if ((threadIdx.x & 31) == 0) { rs[threadIdx.x >> 5] = s; rss[threadIdx.x >> 5] = ss; }
    __syncthreads();
    if (threadIdx.x < 32) {
        s  = (threadIdx.x < 16) ? rs[threadIdx.x]  : 0.f;
        ss = (threadIdx.x < 16) ? rss[threadIdx.x] : 0.f;
#pragma unroll
        for (int o = 8; o > 0; o >>= 1) {
            s  += __shfl_xor_sync(0xffffffffu, s, o);
            ss += __shfl_xor_sync(0xffffffffu, ss, o);
        }
        if (threadIdx.x == 0) {
            const float NEL = (float)(CPG * NTOKB);
            float mean = s / NEL;
            float var  = ss / NEL - mean * mean;
            bc[0] = mean;
            bc[1] = rsqrtf(var + EPS);
        }
    }
    __syncthreads();
    __shared__ float sa[CPG], sb2[CPG];
    if (threadIdx.x < CPG) {
        float a = bc[1] * gw[g * CPG + threadIdx.x];
        sa[threadIdx.x]  = a;
        sb2[threadIdx.x] = gb[g * CPG + threadIdx.x] - bc[0] * a;
    }
    __syncthreads();

    __shared__ float tile[CPG][132];
    const int c  = threadIdx.x >> 5, seg = threadIdx.x & 31;
    const int nl = threadIdx.x >> 2, cq  = threadIdx.x & 3;
    for (int t0 = 0; t0 < NTOKB; t0 += 128) {
        float4 vv = *(const float4*)(xp + (size_t)c * NTOKB + t0 + seg * 4);
        const float a = sa[c], bb = sb2[c];
        tile[c][seg * 4 + 0] = vv.x * a + bb;
        tile[c][seg * 4 + 1] = vv.y * a + bb;
        tile[c][seg * 4 + 2] = vv.z * a + bb;
        tile[c][seg * 4 + 3] = vv.w * a + bb;
        __syncthreads();
        float4 wv;
        wv.x = tile[cq * 4 + 0][nl];
        wv.y = tile[cq * 4 + 1][nl];
        wv.z = tile[cq * 4 + 2][nl];
        wv.w = tile[cq * 4 + 3][nl];
        *(float4*)(g_t + ((size_t)(b * NTOKB + t0 + nl)) * CH + g * CPG + cq * 4) = wv;
        __syncthreads();
    }
}

// ---------------- launch ----------------------------------------------------
extern "C" void kernel_launch(void* const* d_in, const int* in_sizes, int n_in,
                              void* d_out, int out_size)
{
    const float* x  = (const float*)d_in[0];
    const float* gw = (const float*)d_in[1];
    const float* gb = (const float*)d_in[2];
    const float* wq = (const float*)d_in[3];
    const float* bq = (const float*)d_in[4];
    const float* wk = (const float*)d_in[5];
    const float* bk = (const float*)d_in[6];
    const float* wv = (const float*)d_in[7];
    const float* bv = (const float*)d_in[8];
    const float* wo = (const float*)d_in[9];
    const float* bo = (const float*)d_in[10];
    float* out = (float*)d_out;

    float *t, *q, *k, *v, *o;
    cudaGetSymbolAddress((void**)&t, g_t);
    cudaGetSymbolAddress((void**)&q, g_q);
    cudaGetSymbolAddress((void**)&k, g_k);
    cudaGetSymbolAddress((void**)&v, g_v);
    cudaGetSymbolAddress((void**)&o, g_o);

    const int ntBytes = (int)sizeof(NTSm);   // 61,440
    const int bigBytes = (int)sizeof(SM2);   // 92,160
    cudaFuncSetAttribute(gemm_qkv,   cudaFuncAttributeMaxDynamicSharedMemorySize, ntBytes);
    cudaFuncSetAttribute(gemm_out_k, cudaFuncAttributeMaxDynamicSharedMemorySize, ntBytes);
    cudaFuncSetAttribute(gemm_s,     cudaFuncAttributeMaxDynamicSharedMemorySize, bigBytes);
    cudaFuncSetAttribute(gemm_av,    cudaFuncAttributeMaxDynamicSharedMemorySize, bigBytes);

    // 0) zero softmax denominators (graph replays re-run this)
    zero_rowsum_kernel<<<NTOK / 256, 256>>>();

    // 1) GroupNorm -> token layout g_t [B*N, C]
    gn_kernel<<<BATCH * NGROUP, 512>>>(x, gw, gb);

    // 2) fused Q/K/V projections (tf32, 128x128)
    gemm_qkv<<<dim3(CH / 128, NTOK / 128, 3), 256, ntBytes>>>(t, wq, bq, q, wk, bk, k, wv, bv, v);

    // 2b) V -> V^T bf16
    tv_kernel<<<dim3(CH / 32, NTOKB / 32, BATCH), 256>>>(v);

    // 3) S = exp(scale * Q K^T) -> bf16 (tf32, 128x256 big tile)
    gemm_s<<<dim3(NTOKB / 256, NTOKB / 128, BATCH), 256, bigBytes>>>(q, k);

    // 4) O = (P V) / rowsum  (bf16, 128x256 big tile)
    gemm_av<<<dim3(CH / 256, NTOKB / 128, BATCH), 256, bigBytes>>>(o);

    // 5) out = O wo^T + bo, transpose to [B,C,H,W], + residual
    gemm_out_k<<<dim3(CH / 128, NTOK / 128, 1), 256, ntBytes>>>(o, wo, bo, x, out);
}